// round 10
// baseline (speedup 1.0000x reference)
#include <cuda_runtime.h>
#include <cuda_fp16.h>
#include <math.h>

typedef long long ll;
typedef unsigned u32;

#define Bn 8
#define NMELS 128
#define TIN 4096
#define T1 2048
#define S 1024
#define D 1024
#define H 8
#define DH 128
#define Fdim 4096
#define NTOK (Bn*S)
#define Ldim 6

// ---------------- fp32 scratch ----------------
__device__ float g_x [(size_t)NTOK*D];             // residual stream
__device__ float g_bqkv[(size_t)Ldim*3072];        // concatenated qkv bias

// ---------------- fp16 buffers ----------------
__device__ __align__(256) half g_h1[(size_t)Bn*T1*D];   // conv1 out [b][t][d]
__device__ __align__(256) half c1w[(size_t)D*384];
__device__ __align__(256) half c2w[(size_t)D*3072];
__device__ __align__(256) half wqkv[(size_t)Ldim*3072*D];   // [l][3D][D] q|k|v
__device__ __align__(256) half wo[(size_t)Ldim*D*D];
__device__ __align__(256) half w1[(size_t)Ldim*Fdim*D];
__device__ __align__(256) half w2[(size_t)Ldim*Fdim*D];
__device__ __align__(256) half g_col[(size_t)Bn*3072*S];
__device__ __align__(256) half g_y [(size_t)NTOK*D];
__device__ __align__(256) half g_q [(size_t)NTOK*D];
__device__ __align__(256) half g_k [(size_t)NTOK*D];
__device__ __align__(256) half g_vt[(size_t)D*NTOK];
__device__ __align__(256) half g_m1[(size_t)NTOK*Fdim];
__device__ __align__(256) half g_o [(size_t)NTOK*D];

// ---------------- helpers ----------------
__device__ __forceinline__ float gelu_exact(float v) {
    return 0.5f * v * (1.0f + erff(v * 0.70710678118654752f));
}
__device__ __forceinline__ void mma_fp16(float* d, const u32* a, const u32* b) {
    asm volatile(
        "mma.sync.aligned.m16n8k16.row.col.f32.f16.f16.f32 "
        "{%0,%1,%2,%3}, {%4,%5,%6,%7}, {%8,%9}, {%0,%1,%2,%3};\n"
        : "+f"(d[0]), "+f"(d[1]), "+f"(d[2]), "+f"(d[3])
        : "r"(a[0]), "r"(a[1]), "r"(a[2]), "r"(a[3]), "r"(b[0]), "r"(b[1]));
}
__device__ __forceinline__ void ldsm4(u32* r, u32 addr) {
    asm volatile("ldmatrix.sync.aligned.m8n8.x4.shared.b16 {%0,%1,%2,%3}, [%4];\n"
        : "=r"(r[0]), "=r"(r[1]), "=r"(r[2]), "=r"(r[3]) : "r"(addr));
}
__device__ __forceinline__ void cpa16(u32 dst, const void* src) {
    asm volatile("cp.async.cg.shared.global [%0], [%1], 16;\n" :: "r"(dst), "l"(src));
}
__device__ __forceinline__ u32 packh2(float lo, float hi) {
    __half2 h = __floats2half2_rn(lo, hi);
    return *(u32*)&h;
}

// ---------------- fp16 tensor-core GEMM (16 warps, 3-stage cp.async) ----------------
// C[M,N] = A[M,K] * B[N,K]^T
#define KC 32
#define NSTG 3
#define PAD 40
#define TILE_E (128*PAD)
#define STG_B  (2*TILE_E*2)
#define SMEM_TOT (NSTG*STG_B)        // 61440

struct GemmP {
    const half *A, *B;
    float* C; half *Cs;
    half *Qd, *Kd, *Vd;   // qkv fused outputs
    const float* bias;
    int K, lda, ldb, ldc;
    int zDiv;
    ll sAo, sAi, sBo, sBi, sCo, sCi;
    int biasMode;   // 0 none, 1 per-col(n), 2 per-row(m)
    int addC;
    int act;        // 0 none, 1 exact GELU, 2 RoPE+scale
    int transStore;
    int outF32, outHalf;
    int qkvMode;    // fused qkv epilogue
};

__device__ __forceinline__ void rope2(float& v0, float& v1, int m, int cB) {
    int s = m & (S - 1);
    int j = (cB & 127) >> 1;
    float freq = powf(10000.f, -(float)(2 * j) * (1.f / 128.f));
    float ang = (float)s * freq;
    float cc, ss; sincosf(ang, &ss, &cc);
    const float sc = 0.29730177875068026f;  // 128^-0.25
    float r0 = (v0 * cc - v1 * ss) * sc;
    float r1 = (v0 * ss + v1 * cc) * sc;
    v0 = r0; v1 = r1;
}

__global__ __launch_bounds__(512, 1) void gemm_tc(GemmP p) {
    extern __shared__ __align__(16) half sm[];
    int z = blockIdx.z;
    ll offA = (ll)(z / p.zDiv) * p.sAo + (ll)(z % p.zDiv) * p.sAi;
    ll offB = (ll)(z / p.zDiv) * p.sBo + (ll)(z % p.zDiv) * p.sBi;
    ll offC = (ll)(z / p.zDiv) * p.sCo + (ll)(z % p.zDiv) * p.sCi;
    const half* A = p.A + offA;
    const half* B = p.B + offB;

    int m0 = blockIdx.y * 128, n0 = blockIdx.x * 128;
    int tid = threadIdx.x, lane = tid & 31, wid = tid >> 5;
    int wm = (wid & 3) * 32, wn = (wid >> 2) * 32;
    u32 smu = (u32)__cvta_generic_to_shared(sm);

    float acc[2][4][4];
    #pragma unroll
    for (int a = 0; a < 2; a++)
        #pragma unroll
        for (int b = 0; b < 4; b++)
            #pragma unroll
            for (int c = 0; c < 4; c++) acc[a][b][c] = 0.f;

    int ldRow = tid >> 2;
    int ldC   = tid & 3;

    auto issue = [&](int c) {
        u32 base = smu + (u32)(c % NSTG) * STG_B;
        int k0 = c * KC;
        u32 so = (u32)(ldRow * PAD + ldC * 8) * 2;
        ll ao = (ll)(m0 + ldRow) * p.lda + k0 + ldC * 8;
        ll bo = (ll)(n0 + ldRow) * p.ldb + k0 + ldC * 8;
        cpa16(base + 0 * TILE_E * 2 + so, A + ao);
        cpa16(base + 1 * TILE_E * 2 + so, B + bo);
        asm volatile("cp.async.commit_group;" ::: "memory");
    };

    int nch = p.K / KC;
    issue(0);
    if (nch > 1) issue(1);

    for (int c = 0; c < nch; c++) {
        if (c + 1 < nch) asm volatile("cp.async.wait_group 1;" ::: "memory");
        else             asm volatile("cp.async.wait_group 0;" ::: "memory");
        __syncthreads();
        if (c + 2 < nch) issue(c + 2);

        u32 aB = smu + (u32)(c % NSTG) * STG_B;
        u32 bB = aB + TILE_E * 2;

        #pragma unroll
        for (int ks = 0; ks < 2; ks++) {
            u32 ar[2][4], br[4][2];
            #pragma unroll
            for (int mi = 0; mi < 2; mi++) {
                int row = wm + mi * 16 + (lane & 15);
                int col = ks * 16 + (lane >> 4) * 8;
                ldsm4(ar[mi], aB + (u32)(row * PAD + col) * 2);
            }
            #pragma unroll
            for (int nj = 0; nj < 2; nj++) {
                int g = lane >> 3;
                int row = wn + nj * 16 + ((g >> 1) << 3) + (lane & 7);
                int col = ks * 16 + ((g & 1) << 3);
                u32 t[4];
                ldsm4(t, bB + (u32)(row * PAD + col) * 2);
                br[nj*2][0] = t[0]; br[nj*2][1] = t[1];
                br[nj*2+1][0] = t[2]; br[nj*2+1][1] = t[3];
            }
            #pragma unroll
            for (int mi = 0; mi < 2; mi++)
                #pragma unroll
                for (int nf = 0; nf < 4; nf++)
                    mma_fp16(acc[mi][nf], ar[mi], br[nf]);
        }
    }

    float* Cp = p.C  ? p.C  + offC : nullptr;
    half* Csp = p.Cs ? p.Cs + offC : nullptr;
    #pragma unroll
    for (int mi = 0; mi < 2; mi++)
        #pragma unroll
        for (int nf = 0; nf < 4; nf++) {
            int rB = m0 + wm + mi * 16 + (lane >> 2);
            int cB = n0 + wn + nf * 8 + (lane & 3) * 2;
            #pragma unroll
            for (int pe = 0; pe < 2; pe++) {
                int m = rB + pe * 8;
                float v0 = acc[mi][nf][pe * 2 + 0];
                float v1 = acc[mi][nf][pe * 2 + 1];
                if (p.biasMode == 1) { v0 += p.bias[cB]; v1 += p.bias[cB + 1]; }
                else if (p.biasMode == 2) { float bb = p.bias[m]; v0 += bb; v1 += bb; }

                if (p.qkvMode) {
                    int seg = cB >> 10, nn = cB & 1023;
                    if (seg == 0) {
                        rope2(v0, v1, m, cB);
                        *(u32*)&p.Qd[(ll)m * D + nn] = packh2(v0, v1);
                    } else if (seg == 1) {
                        rope2(v0, v1, m, cB);
                        *(u32*)&p.Kd[(ll)m * D + nn] = packh2(v0, v1);
                    } else {
                        p.Vd[(ll)nn * NTOK + m]       = __float2half_rn(v0);
                        p.Vd[(ll)(nn + 1) * NTOK + m] = __float2half_rn(v1);
                    }
                    continue;
                }

                if (p.act == 1) { v0 = gelu_exact(v0); v1 = gelu_exact(v1); }
                else if (p.act == 2) rope2(v0, v1, m, cB);

                if (!p.transStore) {
                    ll off0 = (ll)m * p.ldc + cB;
                    if (p.outF32) {
                        float w0 = v0, w1 = v1;
                        if (p.addC) {
                            float2 o = *(float2*)&Cp[off0];
                            w0 += o.x; w1 += o.y;
                        }
                        *(float2*)&Cp[off0] = make_float2(w0, w1);
                    }
                    if (p.outHalf) *(u32*)&Csp[off0] = packh2(v0, v1);
                } else {
                    ll off0 = (ll)cB * p.ldc + m;
                    ll off1 = off0 + p.ldc;
                    if (p.outF32) {
                        float w0 = v0, w1 = v1;
                        if (p.addC) { w0 += Cp[off0]; w1 += Cp[off1]; }
                        Cp[off0] = w0; Cp[off1] = w1;
                    }
                    if (p.outHalf) {
                        Csp[off0] = __float2half_rn(v0);
                        Csp[off1] = __float2half_rn(v1);
                    }
                }
            }
        }
}

// ---------------- fused flash attention ----------------
// grid (S/64, Bn*H); 128 threads; Q block 64 rows; kv tiles of 128.
// K and V in separate cp.async groups: QK+softmax overlaps the V load.
#define FP2 136
#define FSM_BYTES ((64+128+128)*FP2*2)    // 87040

__global__ __launch_bounds__(128) void attn_k(const int* __restrict__ x_len) {
    extern __shared__ __align__(16) half fsm[];
    int tid = threadIdx.x, lane = tid & 31, wid = tid >> 5;
    int bh = blockIdx.y, b = bh >> 3, h = bh & 7;
    int m0 = blockIdx.x * 64;
    int wm = wid * 16;
    u32 smu = (u32)__cvta_generic_to_shared(fsm);
    u32 sQ = smu;
    u32 sK = smu + (u32)(64 * FP2) * 2;
    u32 sV = sK + (u32)(128 * FP2) * 2;

    const half* qp = g_q + ((ll)(b * S + m0)) * D + h * 128;
    const half* kp = g_k + ((ll)b * S) * D + h * 128;
    const half* vp = g_vt + ((ll)(h * 128)) * NTOK + (ll)b * S;

    // load Q (64 x 128)
    #pragma unroll
    for (int i = 0; i < 8; i++) {
        int idx = tid + 128 * i, row = idx >> 4, ch = idx & 15;
        cpa16(sQ + (u32)(row * FP2 + ch * 8) * 2, qp + (ll)row * D + ch * 8);
    }
    asm volatile("cp.async.commit_group;" ::: "memory");

    int xl = x_len[b];
    int quad = lane >> 2, qi = lane & 3;
    float mrow[2] = {-1e30f, -1e30f}, lrow[2] = {0.f, 0.f};
    float oacc[16][4];
    #pragma unroll
    for (int nt = 0; nt < 16; nt++)
        #pragma unroll
        for (int e = 0; e < 4; e++) oacc[nt][e] = 0.f;

    for (int kv0 = 0; kv0 < S; kv0 += 128) {
        if (kv0) __syncthreads();   // all reads of previous K/V done
        #pragma unroll
        for (int i = 0; i < 16; i++) {
            int idx = tid + 128 * i, row = idx >> 4, ch = idx & 15;
            cpa16(sK + (u32)(row * FP2 + ch * 8) * 2, kp + (ll)(kv0 + row) * D + ch * 8);
        }
        asm volatile("cp.async.commit_group;" ::: "memory");
        #pragma unroll
        for (int i = 0; i < 16; i++) {
            int idx = tid + 128 * i, row = idx >> 4, ch = idx & 15;
            cpa16(sV + (u32)(row * FP2 + ch * 8) * 2, vp + (ll)row * NTOK + kv0 + ch * 8);
        }
        asm volatile("cp.async.commit_group;" ::: "memory");
        asm volatile("cp.async.wait_group 1;" ::: "memory");   // Q(+K) ready; V in flight
        __syncthreads();

        // S = Q @ K^T
        float sacc[16][4];
        #pragma unroll
        for (int nt = 0; nt < 16; nt++)
            #pragma unroll
            for (int e = 0; e < 4; e++) sacc[nt][e] = 0.f;

        #pragma unroll
        for (int ks = 0; ks < 8; ks++) {
            u32 aq[4];
            ldsm4(aq, sQ + (u32)((wm + (lane & 15)) * FP2 + ks * 16 + (lane >> 4) * 8) * 2);
            #pragma unroll
            for (int njp = 0; njp < 8; njp++) {
                int g = lane >> 3;
                int row = njp * 16 + ((g >> 1) << 3) + (lane & 7);
                int col = ks * 16 + ((g & 1) << 3);
                u32 t[4];
                ldsm4(t, sK + (u32)(row * FP2 + col) * 2);
                u32 b0[2] = {t[0], t[1]}, b1[2] = {t[2], t[3]};
                mma_fp16(sacc[njp*2],   aq, b0);
                mma_fp16(sacc[njp*2+1], aq, b1);
            }
        }

        // mask + online softmax (overlaps V load)
        float rmax[2] = {-1e30f, -1e30f};
        #pragma unroll
        for (int nt = 0; nt < 16; nt++)
            #pragma unroll
            for (int e = 0; e < 4; e++) {
                int col = kv0 + nt * 8 + qi * 2 + (e & 1);
                float v = sacc[nt][e] + ((4 * col + 3 < xl) ? 0.f : -1e10f);
                sacc[nt][e] = v;
                rmax[e >> 1] = fmaxf(rmax[e >> 1], v);
            }
        #pragma unroll
        for (int s2 = 1; s2 < 4; s2 <<= 1) {
            rmax[0] = fmaxf(rmax[0], __shfl_xor_sync(0xffffffff, rmax[0], s2));
            rmax[1] = fmaxf(rmax[1], __shfl_xor_sync(0xffffffff, rmax[1], s2));
        }
        float mn0 = fmaxf(mrow[0], rmax[0]), mn1 = fmaxf(mrow[1], rmax[1]);
        float sc0 = expf(mrow[0] - mn0), sc1 = expf(mrow[1] - mn1);
        float rsum[2] = {0.f, 0.f};
        #pragma unroll
        for (int nt = 0; nt < 16; nt++)
            #pragma unroll
            for (int e = 0; e < 4; e++) {
                float v = expf(sacc[nt][e] - ((e >> 1) ? mn1 : mn0));
                sacc[nt][e] = v;
                rsum[e >> 1] += v;
            }
        #pragma unroll
        for (int s2 = 1; s2 < 4; s2 <<= 1) {
            rsum[0] += __shfl_xor_sync(0xffffffff, rsum[0], s2);
            rsum[1] += __shfl_xor_sync(0xffffffff, rsum[1], s2);
        }
        lrow[0] = lrow[0] * sc0 + rsum[0];
        lrow[1] = lrow[1] * sc1 + rsum[1];
        mrow[0] = mn0; mrow[1] = mn1;
        #pragma unroll
        for (int nt = 0; nt < 16; nt++) {
            oacc[nt][0] *= sc0; oacc[nt][1] *= sc0;
            oacc[nt][2] *= sc1; oacc[nt][3] *= sc1;
        }

        asm volatile("cp.async.wait_group 0;" ::: "memory");   // V ready
        __syncthreads();

        // O += P @ V
        #pragma unroll
        for (int j = 0; j < 8; j++) {
            u32 af[4];
            af[0] = packh2(sacc[2*j][0],   sacc[2*j][1]);
            af[1] = packh2(sacc[2*j][2],   sacc[2*j][3]);
            af[2] = packh2(sacc[2*j+1][0], sacc[2*j+1][1]);
            af[3] = packh2(sacc[2*j+1][2], sacc[2*j+1][3]);
            #pragma unroll
            for (int njp = 0; njp < 8; njp++) {
                int g = lane >> 3;
                int row = njp * 16 + ((g >> 1) << 3) + (lane & 7);
                int col = j * 16 + ((g & 1) << 3);
                u32 t[4];
                ldsm4(t, sV + (u32)(row * FP2 + col) * 2);
                u32 b0[2] = {t[0], t[1]}, b1[2] = {t[2], t[3]};
                mma_fp16(oacc[njp*2],   af, b0);
                mma_fp16(oacc[njp*2+1], af, b1);
            }
        }
    }

    float inv0 = 1.f / lrow[0], inv1 = 1.f / lrow[1];
    half* op = g_o + ((ll)(b * S + m0 + wm)) * D + h * 128;
    #pragma unroll
    for (int nt = 0; nt < 16; nt++)
        #pragma unroll
        for (int pe = 0; pe < 2; pe++) {
            int row = quad + pe * 8;
            float iv = pe ? inv1 : inv0;
            u32 pk = packh2(oacc[nt][pe*2] * iv, oacc[nt][pe*2+1] * iv);
            *(u32*)&op[(ll)row * D + nt * 8 + qi * 2] = pk;
        }
}

// ---------------- weight converts ----------------
__global__ void cvt_k(const float* __restrict__ in, half* __restrict__ out, ll n) {
    ll i = ((ll)blockIdx.x * 256 + threadIdx.x) * 4;
    if (i >= n) return;
    float4 v = *(const float4*)&in[i];
    out[i+0] = __float2half_rn(v.x);
    out[i+1] = __float2half_rn(v.y);
    out[i+2] = __float2half_rn(v.z);
    out[i+3] = __float2half_rn(v.w);
}
__global__ void cvt_qkv_k(const float* __restrict__ qw, const float* __restrict__ kw,
                          const float* __restrict__ vw, half* __restrict__ out) {
    ll i = ((ll)blockIdx.x * 256 + threadIdx.x) * 4;
    const ll total = (ll)Ldim * 3072 * D;
    if (i >= total) return;
    int col = (int)(i & 1023);
    int row = (int)((i >> 10) % 3072);
    int l   = (int)(i / ((ll)3072 * 1024));
    const float* src;
    if (row < 1024)      src = qw + ((ll)l * 1024 + row) * 1024 + col;
    else if (row < 2048) src = kw + ((ll)l * 1024 + row - 1024) * 1024 + col;
    else                 src = vw + ((ll)l * 1024 + row - 2048) * 1024 + col;
    float4 v = *(const float4*)src;
    out[i+0] = __float2half_rn(v.x);
    out[i+1] = __float2half_rn(v.y);
    out[i+2] = __float2half_rn(v.z);
    out[i+3] = __float2half_rn(v.w);
}
__global__ void bqkv_k(const float* __restrict__ qb, const float* __restrict__ vb) {
    int i = blockIdx.x * 256 + threadIdx.x;
    if (i >= Ldim * 3072) return;
    int l = i / 3072, r = i % 3072;
    float v = 0.f;
    if (r < 1024)       v = qb[l * 1024 + r];
    else if (r >= 2048) v = vb[l * 1024 + r - 2048];
    g_bqkv[i] = v;
}

// ---------------- im2col ----------------
__global__ void im2col1_k(const float* __restrict__ x) {
    int idx = blockIdx.x * 256 + threadIdx.x;
    const int total = Bn * T1 * 384;
    if (idx >= total) return;
    int r = idx % 384;
    int t = (idx / 384) % T1;
    int b = idx / (384 * T1);
    int i = r / 3, kk = r % 3;
    int pos = 2 * t + kk - 1;
    float v = (pos >= 0 && pos < TIN) ? x[((ll)b * NMELS + i) * TIN + pos] : 0.f;
    g_col[idx] = __float2half_rn(v);
}
__global__ void im2col2_k() {
    ll idx = (ll)blockIdx.x * 256 + threadIdx.x;
    const ll total = (ll)Bn * S * 3072;
    if (idx >= total) return;
    int r = (int)(idx % 3072);
    int t = (int)((idx / 3072) % S);
    int b = (int)(idx / ((ll)S * 3072));
    int i = r / 3, kk = r % 3;
    int pos = 2 * t + kk - 1;
    g_col[idx] = (pos >= 0 && pos < T1) ? g_h1[((ll)b * T1 + pos) * D + i] : __float2half_rn(0.f);
}

// ---------------- LayerNorm -> fp16 ----------------
__global__ void ln_k(const float* __restrict__ x,
                     const float* __restrict__ w, const float* __restrict__ b) {
    int row = blockIdx.x;
    int tid = threadIdx.x;
    const float* xr = x + (ll)row * D;
    __shared__ float red[256];
    float v[4];
    #pragma unroll
    for (int i = 0; i < 4; i++) v[i] = xr[tid + 256 * i];
    float s = v[0] + v[1] + v[2] + v[3];
    red[tid] = s; __syncthreads();
    for (int o = 128; o > 0; o >>= 1) { if (tid < o) red[tid] += red[tid + o]; __syncthreads(); }
    float mean = red[0] * (1.f / D);
    __syncthreads();
    float sq = 0.f;
    #pragma unroll
    for (int i = 0; i < 4; i++) { float d0 = v[i] - mean; sq += d0 * d0; }
    red[tid] = sq; __syncthreads();
    for (int o = 128; o > 0; o >>= 1) { if (tid < o) red[tid] += red[tid + o]; __syncthreads(); }
    float rstd = rsqrtf(red[0] * (1.f / D) + 1e-5f);
    #pragma unroll
    for (int i = 0; i < 4; i++) {
        int c = tid + 256 * i;
        float y = (v[i] - mean) * rstd * w[c] + b[c];
        g_y[(ll)row * D + c] = __float2half_rn(y);
    }
}

// ---------------- output ----------------
__global__ void out_k(float* __restrict__ out, const int* __restrict__ x_len, ll out_size) {
    ll i = (ll)blockIdx.x * 256 + threadIdx.x;
    const ll nh = (ll)NTOK * D;
    if (i < nh && i < out_size) out[i] = g_x[i];
    if (i < Bn) {
        ll pos = nh + i;
        if (pos < out_size) {
            int yl = (x_len[i] + 1) / 2;
            yl = (yl + 1) / 2;
            out[pos] = (float)yl;
        }
    }
}

// ---------------- host launcher ----------------
extern "C" void kernel_launch(void* const* d_in, const int* in_sizes, int n_in,
                              void* d_out, int out_size) {
    const float* x        = (const float*)d_in[0];
    const int*   x_len    = (const int*)  d_in[1];
    const float* conv1_w  = (const float*)d_in[2];
    const float* conv1_b  = (const float*)d_in[3];
    const float* conv2_w  = (const float*)d_in[4];
    const float* conv2_b  = (const float*)d_in[5];
    const float* attn_ln_w= (const float*)d_in[6];
    const float* attn_ln_b= (const float*)d_in[7];
    const float* q_w      = (const float*)d_in[8];
    const float* q_b      = (const float*)d_in[9];
    const float* k_w      = (const float*)d_in[10];
    const float* v_w      = (const float*)d_in[11];
    const float* v_b      = (const float*)d_in[12];
    const float* out_w    = (const float*)d_in[13];
    const float* out_b    = (const float*)d_in[14];
    const float* mlp_ln_w = (const float*)d_in[15];
    const float* mlp_ln_b = (const float*)d_in[16];
    const float* mlp1_w   = (const float*)d_in[17];
    const float* mlp1_b   = (const float*)d_in[18];
    const float* mlp2_w   = (const float*)d_in[19];
    const float* mlp2_b   = (const float*)d_in[20];

    cudaFuncSetAttribute(gemm_tc, cudaFuncAttributeMaxDynamicSharedMemorySize, SMEM_TOT);
    cudaFuncSetAttribute(attn_k,  cudaFuncAttributeMaxDynamicSharedMemorySize, FSM_BYTES);

    #define SYM(p, s) do { void* _t; cudaGetSymbolAddress(&_t, s); p = (decltype(p))_t; } while (0)
    float *xs, *pbqkv;
    SYM(xs, g_x); SYM(pbqkv, g_bqkv);
    half *ph1, *pc1, *pc2, *pwqkv, *pwo, *pw1, *pw2;
    half *pcol, *py, *pq, *pk, *pvt, *pm1, *po;
    SYM(ph1, g_h1);
    SYM(pc1, c1w); SYM(pc2, c2w);
    SYM(pwqkv, wqkv); SYM(pwo, wo);
    SYM(pw1, w1); SYM(pw2, w2);
    SYM(pcol, g_col); SYM(py, g_y); SYM(pq, g_q); SYM(pk, g_k);
    SYM(pvt, g_vt); SYM(pm1, g_m1); SYM(po, g_o);

    auto cvt = [&](const float* in, half* out, ll n) {
        cvt_k<<<(int)((n / 4 + 255) / 256), 256>>>(in, out, n);
    };
    cvt(conv1_w, pc1, (ll)D * 384);
    cvt(conv2_w, pc2, (ll)D * 3072);
    cvt_qkv_k<<<(int)(((ll)Ldim * 3072 * D / 4 + 255) / 256), 256>>>(q_w, k_w, v_w, pwqkv);
    bqkv_k<<<(Ldim * 3072 + 255) / 256, 256>>>(q_b, v_b);
    cvt(out_w, pwo, (ll)Ldim * D * D);
    cvt(mlp1_w, pw1, (ll)Ldim * Fdim * D);
    cvt(mlp2_w, pw2, (ll)Ldim * Fdim * D);

    auto gemm = [&](const half* A, const half* B,
                    float* C, half* Cs, const float* bias,
                    int M, int N, int K, int lda, int ldb, int ldc,
                    int nz, int zDiv,
                    ll sAo, ll sAi, ll sBo, ll sBi, ll sCo, ll sCi,
                    int biasMode, int addC, int act, int transStore,
                    int outF32, int outHalf, int qkvMode = 0,
                    half* Qd = 0, half* Kd = 0, half* Vd = 0) {
        GemmP p;
        p.A = A; p.B = B;
        p.C = C; p.Cs = Cs; p.bias = bias;
        p.Qd = Qd; p.Kd = Kd; p.Vd = Vd;
        p.K = K; p.lda = lda; p.ldb = ldb; p.ldc = ldc;
        p.zDiv = zDiv;
        p.sAo = sAo; p.sAi = sAi; p.sBo = sBo; p.sBi = sBi; p.sCo = sCo; p.sCi = sCi;
        p.biasMode = biasMode; p.addC = addC; p.act = act;
        p.transStore = transStore;
        p.outF32 = outF32; p.outHalf = outHalf; p.qkvMode = qkvMode;
        dim3 g(N / 128, M / 128, nz);
        gemm_tc<<<g, 512, SMEM_TOT>>>(p);
    };

    const ll SD = (ll)S * D;

    // conv1
    im2col1_k<<<(Bn * T1 * 384 + 255) / 256, 256>>>(x);
    gemm(pcol, pc1, 0, ph1, conv1_b,
         T1, 1024, 384, 384, 384, D,
         Bn, 1, (ll)T1 * 384, 0, 0, 0, (ll)T1 * D, 0,
         1, 0, 1, 0, 0, 1);

    // conv2
    im2col2_k<<<(int)(((ll)Bn * S * 3072 + 255) / 256), 256>>>();
    gemm(pcol, pc2, xs, 0, conv2_b,
         S, 1024, 3072, 3072, 3072, D,
         Bn, 1, (ll)S * 3072, 0, 0, 0, SD, 0,
         1, 0, 1, 0, 1, 0);

    for (int l = 0; l < 6; l++) {
        const float* aw = attn_ln_w + l * D;  const float* ab = attn_ln_b + l * D;
        const float* ob = out_b + l * D;
        const float* mw = mlp_ln_w + l * D;   const float* mb2 = mlp_ln_b + l * D;
        const float* b1 = mlp1_b + l * Fdim;
        const float* b2 = mlp2_b + l * D;
        ll wOff = (ll)l * D * D;
        ll mOff = (ll)l * Fdim * D;

        ln_k<<<NTOK, 256>>>(xs, aw, ab);

        // fused qkv projection: N=3072, epilogue routes q(RoPE)/k(RoPE)/v(transposed)
        gemm(py, pwqkv + (ll)l * 3072 * D, 0, 0, pbqkv + (ll)l * 3072,
             NTOK, 3072, D, D, D, D, 1, 1, 0,0,0,0,0,0,
             1, 0, 0, 0, 0, 0, 1, pq, pk, pvt);

        // fused flash attention -> g_o fp16
        attn_k<<<dim3(S / 64, Bn * H), 128, FSM_BYTES>>>(x_len);

        // out projection + residual
        gemm(po, pwo + wOff, xs, 0, ob,
             NTOK, D, D, D, D, D, 1, 1, 0,0,0,0,0,0, 1, 1, 0, 0, 1, 0);

        // MLP
        ln_k<<<NTOK, 256>>>(xs, mw, mb2);
        gemm(py, pw1 + mOff, 0, pm1, b1,
             NTOK, Fdim, D, D, D, Fdim, 1, 1, 0,0,0,0,0,0, 1, 0, 1, 0, 0, 1);
        gemm(pm1, pw2 + mOff, xs, 0, b2,
             NTOK, D, Fdim, Fdim, Fdim, D, 1, 1, 0,0,0,0,0,0, 1, 1, 0, 0, 1, 0);
    }

    ll nh = (ll)NTOK * D;
    out_k<<<(int)((nh + 255) / 256), 256>>>((float*)d_out, x_len, (ll)out_size);
}

// round 11
// speedup vs baseline: 1.0383x; 1.0383x over previous
#include <cuda_runtime.h>
#include <cuda_fp16.h>
#include <math.h>

typedef long long ll;
typedef unsigned u32;

#define Bn 8
#define NMELS 128
#define TIN 4096
#define T1 2048
#define S 1024
#define D 1024
#define H 8
#define DH 128
#define Fdim 4096
#define NTOK (Bn*S)
#define Ldim 6

// ---------------- fp32 scratch ----------------
__device__ float g_x [(size_t)NTOK*D];             // residual stream

// ---------------- fp16 buffers ----------------
__device__ __align__(256) half g_h1[(size_t)Bn*T1*D];   // conv1 out [b][t][d]
__device__ __align__(256) half c1w[(size_t)D*384];
__device__ __align__(256) half c2w[(size_t)D*3072];
__device__ __align__(256) half wq[(size_t)Ldim*D*D];
__device__ __align__(256) half wk[(size_t)Ldim*D*D];
__device__ __align__(256) half wv[(size_t)Ldim*D*D];
__device__ __align__(256) half wo[(size_t)Ldim*D*D];
__device__ __align__(256) half w1[(size_t)Ldim*Fdim*D];
__device__ __align__(256) half w2[(size_t)Ldim*Fdim*D];
__device__ __align__(256) half g_col[(size_t)Bn*3072*S];
__device__ __align__(256) half g_y [(size_t)NTOK*D];
__device__ __align__(256) half g_q [(size_t)NTOK*D];
__device__ __align__(256) half g_k [(size_t)NTOK*D];
__device__ __align__(256) half g_vt[(size_t)D*NTOK];
__device__ __align__(256) half g_m1[(size_t)NTOK*Fdim];
__device__ __align__(256) half g_o [(size_t)NTOK*D];

// ---------------- helpers ----------------
__device__ __forceinline__ float gelu_exact(float v) {
    return 0.5f * v * (1.0f + erff(v * 0.70710678118654752f));
}
__device__ __forceinline__ void mma_fp16(float* d, const u32* a, const u32* b) {
    asm volatile(
        "mma.sync.aligned.m16n8k16.row.col.f32.f16.f16.f32 "
        "{%0,%1,%2,%3}, {%4,%5,%6,%7}, {%8,%9}, {%0,%1,%2,%3};\n"
        : "+f"(d[0]), "+f"(d[1]), "+f"(d[2]), "+f"(d[3])
        : "r"(a[0]), "r"(a[1]), "r"(a[2]), "r"(a[3]), "r"(b[0]), "r"(b[1]));
}
__device__ __forceinline__ void ldsm4(u32* r, u32 addr) {
    asm volatile("ldmatrix.sync.aligned.m8n8.x4.shared.b16 {%0,%1,%2,%3}, [%4];\n"
        : "=r"(r[0]), "=r"(r[1]), "=r"(r[2]), "=r"(r[3]) : "r"(addr));
}
__device__ __forceinline__ void cpa16(u32 dst, const void* src) {
    asm volatile("cp.async.cg.shared.global [%0], [%1], 16;\n" :: "r"(dst), "l"(src));
}
__device__ __forceinline__ u32 packh2(float lo, float hi) {
    __half2 h = __floats2half2_rn(lo, hi);
    return *(u32*)&h;
}

// ---------------- fp16 tensor-core GEMM (16 warps, 3-stage cp.async) ----------------
// C[M,N] = A[M,K] * B[N,K]^T
#define KC 32
#define NSTG 3
#define PAD 40
#define TILE_E (128*PAD)
#define STG_B  (2*TILE_E*2)
#define SMEM_TOT (NSTG*STG_B)        // 61440

struct GemmP {
    const half *A, *B;
    float* C; half *Cs;
    const float* Cin;   // residual source (defaults to C)
    const float* bias;
    int K, lda, ldb, ldc;
    int zDiv;
    ll sAo, sAi, sBo, sBi, sCo, sCi;
    int biasMode;   // 0 none, 1 per-col(n), 2 per-row(m)
    int addC;
    int act;        // 0 none, 1 exact GELU, 2 RoPE+scale
    int transStore;
    int outF32, outHalf;
};

__global__ __launch_bounds__(512, 1) void gemm_tc(GemmP p) {
    extern __shared__ __align__(16) half sm[];
    int z = blockIdx.z;
    ll offA = (ll)(z / p.zDiv) * p.sAo + (ll)(z % p.zDiv) * p.sAi;
    ll offB = (ll)(z / p.zDiv) * p.sBo + (ll)(z % p.zDiv) * p.sBi;
    ll offC = (ll)(z / p.zDiv) * p.sCo + (ll)(z % p.zDiv) * p.sCi;
    const half* A = p.A + offA;
    const half* B = p.B + offB;

    int m0 = blockIdx.y * 128, n0 = blockIdx.x * 128;
    int tid = threadIdx.x, lane = tid & 31, wid = tid >> 5;
    int wm = (wid & 3) * 32, wn = (wid >> 2) * 32;
    u32 smu = (u32)__cvta_generic_to_shared(sm);

    float acc[2][4][4];
    #pragma unroll
    for (int a = 0; a < 2; a++)
        #pragma unroll
        for (int b = 0; b < 4; b++)
            #pragma unroll
            for (int c = 0; c < 4; c++) acc[a][b][c] = 0.f;

    int ldRow = tid >> 2;
    int ldC   = tid & 3;

    auto issue = [&](int c) {
        u32 base = smu + (u32)(c % NSTG) * STG_B;
        int k0 = c * KC;
        u32 so = (u32)(ldRow * PAD + ldC * 8) * 2;
        ll ao = (ll)(m0 + ldRow) * p.lda + k0 + ldC * 8;
        ll bo = (ll)(n0 + ldRow) * p.ldb + k0 + ldC * 8;
        cpa16(base + 0 * TILE_E * 2 + so, A + ao);
        cpa16(base + 1 * TILE_E * 2 + so, B + bo);
        asm volatile("cp.async.commit_group;" ::: "memory");
    };

    int nch = p.K / KC;
    issue(0);
    if (nch > 1) issue(1);

    for (int c = 0; c < nch; c++) {
        if (c + 1 < nch) asm volatile("cp.async.wait_group 1;" ::: "memory");
        else             asm volatile("cp.async.wait_group 0;" ::: "memory");
        __syncthreads();
        if (c + 2 < nch) issue(c + 2);

        u32 aB = smu + (u32)(c % NSTG) * STG_B;
        u32 bB = aB + TILE_E * 2;

        #pragma unroll
        for (int ks = 0; ks < 2; ks++) {
            u32 ar[2][4], br[4][2];
            #pragma unroll
            for (int mi = 0; mi < 2; mi++) {
                int row = wm + mi * 16 + (lane & 15);
                int col = ks * 16 + (lane >> 4) * 8;
                ldsm4(ar[mi], aB + (u32)(row * PAD + col) * 2);
            }
            #pragma unroll
            for (int nj = 0; nj < 2; nj++) {
                int g = lane >> 3;
                int row = wn + nj * 16 + ((g >> 1) << 3) + (lane & 7);
                int col = ks * 16 + ((g & 1) << 3);
                u32 t[4];
                ldsm4(t, bB + (u32)(row * PAD + col) * 2);
                br[nj*2][0] = t[0]; br[nj*2][1] = t[1];
                br[nj*2+1][0] = t[2]; br[nj*2+1][1] = t[3];
            }
            #pragma unroll
            for (int mi = 0; mi < 2; mi++)
                #pragma unroll
                for (int nf = 0; nf < 4; nf++)
                    mma_fp16(acc[mi][nf], ar[mi], br[nf]);
        }
    }

    float* Cp = p.C  ? p.C  + offC : nullptr;
    half* Csp = p.Cs ? p.Cs + offC : nullptr;
    const float* Rp = p.Cin ? p.Cin + offC : Cp;
    #pragma unroll
    for (int mi = 0; mi < 2; mi++)
        #pragma unroll
        for (int nf = 0; nf < 4; nf++) {
            int rB = m0 + wm + mi * 16 + (lane >> 2);
            int cB = n0 + wn + nf * 8 + (lane & 3) * 2;
            #pragma unroll
            for (int pe = 0; pe < 2; pe++) {
                int m = rB + pe * 8;
                float v0 = acc[mi][nf][pe * 2 + 0];
                float v1 = acc[mi][nf][pe * 2 + 1];
                if (p.biasMode == 1) { v0 += p.bias[cB]; v1 += p.bias[cB + 1]; }
                else if (p.biasMode == 2) { float bb = p.bias[m]; v0 += bb; v1 += bb; }
                if (p.act == 1) { v0 = gelu_exact(v0); v1 = gelu_exact(v1); }
                else if (p.act == 2) {
                    int s = m & (S - 1);
                    int j = (cB & 127) >> 1;
                    float freq = powf(10000.f, -(float)(2 * j) * (1.f / 128.f));
                    float ang = (float)s * freq;
                    float cc, ss; sincosf(ang, &ss, &cc);
                    const float sc = 0.29730177875068026f;  // 128^-0.25
                    float r0 = (v0 * cc - v1 * ss) * sc;
                    float r1 = (v0 * ss + v1 * cc) * sc;
                    v0 = r0; v1 = r1;
                }
                if (!p.transStore) {
                    ll off0 = (ll)m * p.ldc + cB;
                    if (p.outF32) {
                        float w0 = v0, w1 = v1;
                        if (p.addC) {
                            float2 o = *(const float2*)&Rp[off0];
                            w0 += o.x; w1 += o.y;
                        }
                        *(float2*)&Cp[off0] = make_float2(w0, w1);
                    }
                    if (p.outHalf) *(u32*)&Csp[off0] = packh2(v0, v1);
                } else {
                    ll off0 = (ll)cB * p.ldc + m;
                    ll off1 = off0 + p.ldc;
                    if (p.outF32) {
                        float w0 = v0, w1 = v1;
                        if (p.addC) { w0 += Rp[off0]; w1 += Rp[off1]; }
                        Cp[off0] = w0; Cp[off1] = w1;
                    }
                    if (p.outHalf) {
                        Csp[off0] = __float2half_rn(v0);
                        Csp[off1] = __float2half_rn(v1);
                    }
                }
            }
        }
}

// ---------------- fused flash attention ----------------
// grid (S/128, Bn*H); 256 threads (8 warps x 16 rows); kv tiles of 128.
// K and V in separate commit groups: QK+softmax overlaps the V load.
#define FP2 136
#define FSM_BYTES ((128+128+128)*FP2*2)    // 104448

__global__ __launch_bounds__(256) void attn_k(const int* __restrict__ x_len) {
    extern __shared__ __align__(16) half fsm[];
    int tid = threadIdx.x, lane = tid & 31, wid = tid >> 5;
    int bh = blockIdx.y, b = bh >> 3, h = bh & 7;
    int m0 = blockIdx.x * 128;
    int wm = wid * 16;
    u32 smu = (u32)__cvta_generic_to_shared(fsm);
    u32 sQ = smu;
    u32 sK = smu + (u32)(128 * FP2) * 2;
    u32 sV = sK + (u32)(128 * FP2) * 2;

    const half* qp = g_q + ((ll)(b * S + m0)) * D + h * 128;
    const half* kp = g_k + ((ll)b * S) * D + h * 128;
    const half* vp = g_vt + ((ll)(h * 128)) * NTOK + (ll)b * S;

    // load Q (128 x 128)
    #pragma unroll
    for (int i = 0; i < 8; i++) {
        int idx = tid + 256 * i, row = idx >> 4, ch = idx & 15;
        cpa16(sQ + (u32)(row * FP2 + ch * 8) * 2, qp + (ll)row * D + ch * 8);
    }
    asm volatile("cp.async.commit_group;" ::: "memory");

    int xl = x_len[b];
    int quad = lane >> 2, qi = lane & 3;
    float mrow[2] = {-1e30f, -1e30f}, lrow[2] = {0.f, 0.f};
    float oacc[16][4];
    #pragma unroll
    for (int nt = 0; nt < 16; nt++)
        #pragma unroll
        for (int e = 0; e < 4; e++) oacc[nt][e] = 0.f;

    for (int kv0 = 0; kv0 < S; kv0 += 128) {
        if (kv0) __syncthreads();   // all reads of previous K/V done
        #pragma unroll
        for (int i = 0; i < 8; i++) {
            int idx = tid + 256 * i, row = idx >> 4, ch = idx & 15;
            cpa16(sK + (u32)(row * FP2 + ch * 8) * 2, kp + (ll)(kv0 + row) * D + ch * 8);
        }
        asm volatile("cp.async.commit_group;" ::: "memory");
        #pragma unroll
        for (int i = 0; i < 8; i++) {
            int idx = tid + 256 * i, row = idx >> 4, ch = idx & 15;
            cpa16(sV + (u32)(row * FP2 + ch * 8) * 2, vp + (ll)row * NTOK + kv0 + ch * 8);
        }
        asm volatile("cp.async.commit_group;" ::: "memory");
        asm volatile("cp.async.wait_group 1;" ::: "memory");   // Q+K ready; V in flight
        __syncthreads();

        // S = Q @ K^T (each warp: 16 rows x 128 cols)
        float sacc[16][4];
        #pragma unroll
        for (int nt = 0; nt < 16; nt++)
            #pragma unroll
            for (int e = 0; e < 4; e++) sacc[nt][e] = 0.f;

        #pragma unroll
        for (int ks = 0; ks < 8; ks++) {
            u32 aq[4];
            ldsm4(aq, sQ + (u32)((wm + (lane & 15)) * FP2 + ks * 16 + (lane >> 4) * 8) * 2);
            #pragma unroll
            for (int njp = 0; njp < 8; njp++) {
                int g = lane >> 3;
                int row = njp * 16 + ((g >> 1) << 3) + (lane & 7);
                int col = ks * 16 + ((g & 1) << 3);
                u32 t[4];
                ldsm4(t, sK + (u32)(row * FP2 + col) * 2);
                u32 b0[2] = {t[0], t[1]}, b1[2] = {t[2], t[3]};
                mma_fp16(sacc[njp*2],   aq, b0);
                mma_fp16(sacc[njp*2+1], aq, b1);
            }
        }

        // mask + online softmax (overlaps V load)
        float rmax[2] = {-1e30f, -1e30f};
        #pragma unroll
        for (int nt = 0; nt < 16; nt++)
            #pragma unroll
            for (int e = 0; e < 4; e++) {
                int col = kv0 + nt * 8 + qi * 2 + (e & 1);
                float v = sacc[nt][e] + ((4 * col + 3 < xl) ? 0.f : -1e10f);
                sacc[nt][e] = v;
                rmax[e >> 1] = fmaxf(rmax[e >> 1], v);
            }
        #pragma unroll
        for (int s2 = 1; s2 < 4; s2 <<= 1) {
            rmax[0] = fmaxf(rmax[0], __shfl_xor_sync(0xffffffff, rmax[0], s2));
            rmax[1] = fmaxf(rmax[1], __shfl_xor_sync(0xffffffff, rmax[1], s2));
        }
        float mn0 = fmaxf(mrow[0], rmax[0]), mn1 = fmaxf(mrow[1], rmax[1]);
        float sc0 = expf(mrow[0] - mn0), sc1 = expf(mrow[1] - mn1);
        float rsum[2] = {0.f, 0.f};
        #pragma unroll
        for (int nt = 0; nt < 16; nt++)
            #pragma unroll
            for (int e = 0; e < 4; e++) {
                float v = expf(sacc[nt][e] - ((e >> 1) ? mn1 : mn0));
                sacc[nt][e] = v;
                rsum[e >> 1] += v;
            }
        #pragma unroll
        for (int s2 = 1; s2 < 4; s2 <<= 1) {
            rsum[0] += __shfl_xor_sync(0xffffffff, rsum[0], s2);
            rsum[1] += __shfl_xor_sync(0xffffffff, rsum[1], s2);
        }
        lrow[0] = lrow[0] * sc0 + rsum[0];
        lrow[1] = lrow[1] * sc1 + rsum[1];
        mrow[0] = mn0; mrow[1] = mn1;
        #pragma unroll
        for (int nt = 0; nt < 16; nt++) {
            oacc[nt][0] *= sc0; oacc[nt][1] *= sc0;
            oacc[nt][2] *= sc1; oacc[nt][3] *= sc1;
        }

        asm volatile("cp.async.wait_group 0;" ::: "memory");   // V ready
        __syncthreads();

        // O += P @ V
        #pragma unroll
        for (int j = 0; j < 8; j++) {
            u32 af[4];
            af[0] = packh2(sacc[2*j][0],   sacc[2*j][1]);
            af[1] = packh2(sacc[2*j][2],   sacc[2*j][3]);
            af[2] = packh2(sacc[2*j+1][0], sacc[2*j+1][1]);
            af[3] = packh2(sacc[2*j+1][2], sacc[2*j+1][3]);
            #pragma unroll
            for (int njp = 0; njp < 8; njp++) {
                int g = lane >> 3;
                int row = njp * 16 + ((g >> 1) << 3) + (lane & 7);
                int col = j * 16 + ((g & 1) << 3);
                u32 t[4];
                ldsm4(t, sV + (u32)(row * FP2 + col) * 2);
                u32 b0[2] = {t[0], t[1]}, b1[2] = {t[2], t[3]};
                mma_fp16(oacc[njp*2],   af, b0);
                mma_fp16(oacc[njp*2+1], af, b1);
            }
        }
    }

    float inv0 = 1.f / lrow[0], inv1 = 1.f / lrow[1];
    half* op = g_o + ((ll)(b * S + m0 + wm)) * D + h * 128;
    #pragma unroll
    for (int nt = 0; nt < 16; nt++)
        #pragma unroll
        for (int pe = 0; pe < 2; pe++) {
            int row = quad + pe * 8;
            float iv = pe ? inv1 : inv0;
            u32 pk = packh2(oacc[nt][pe*2] * iv, oacc[nt][pe*2+1] * iv);
            *(u32*)&op[(ll)row * D + nt * 8 + qi * 2] = pk;
        }
}

// ---------------- weight convert fp32 -> fp16 ----------------
__global__ void cvt_k(const float* __restrict__ in, half* __restrict__ out, ll n) {
    ll i = ((ll)blockIdx.x * 256 + threadIdx.x) * 4;
    if (i >= n) return;
    float4 v = *(const float4*)&in[i];
    out[i+0] = __float2half_rn(v.x);
    out[i+1] = __float2half_rn(v.y);
    out[i+2] = __float2half_rn(v.z);
    out[i+3] = __float2half_rn(v.w);
}

// ---------------- im2col ----------------
__global__ void im2col1_k(const float* __restrict__ x) {
    int idx = blockIdx.x * 256 + threadIdx.x;
    const int total = Bn * T1 * 384;
    if (idx >= total) return;
    int r = idx % 384;
    int t = (idx / 384) % T1;
    int b = idx / (384 * T1);
    int i = r / 3, kk = r % 3;
    int pos = 2 * t + kk - 1;
    float v = (pos >= 0 && pos < TIN) ? x[((ll)b * NMELS + i) * TIN + pos] : 0.f;
    g_col[idx] = __float2half_rn(v);
}
__global__ void im2col2_k() {
    ll idx = (ll)blockIdx.x * 256 + threadIdx.x;
    const ll total = (ll)Bn * S * 3072;
    if (idx >= total) return;
    int r = (int)(idx % 3072);
    int t = (int)((idx / 3072) % S);
    int b = (int)(idx / ((ll)S * 3072));
    int i = r / 3, kk = r % 3;
    int pos = 2 * t + kk - 1;
    g_col[idx] = (pos >= 0 && pos < T1) ? g_h1[((ll)b * T1 + pos) * D + i] : __float2half_rn(0.f);
}

// ---------------- LayerNorm -> fp16 ----------------
__global__ void ln_k(const float* __restrict__ x,
                     const float* __restrict__ w, const float* __restrict__ b) {
    int row = blockIdx.x;
    int tid = threadIdx.x;
    const float* xr = x + (ll)row * D;
    __shared__ float red[256];
    float v[4];
    #pragma unroll
    for (int i = 0; i < 4; i++) v[i] = xr[tid + 256 * i];
    float s = v[0] + v[1] + v[2] + v[3];
    red[tid] = s; __syncthreads();
    for (int o = 128; o > 0; o >>= 1) { if (tid < o) red[tid] += red[tid + o]; __syncthreads(); }
    float mean = red[0] * (1.f / D);
    __syncthreads();
    float sq = 0.f;
    #pragma unroll
    for (int i = 0; i < 4; i++) { float d0 = v[i] - mean; sq += d0 * d0; }
    red[tid] = sq; __syncthreads();
    for (int o = 128; o > 0; o >>= 1) { if (tid < o) red[tid] += red[tid + o]; __syncthreads(); }
    float rstd = rsqrtf(red[0] * (1.f / D) + 1e-5f);
    #pragma unroll
    for (int i = 0; i < 4; i++) {
        int c = tid + 256 * i;
        float y = (v[i] - mean) * rstd * w[c] + b[c];
        g_y[(ll)row * D + c] = __float2half_rn(y);
    }
}

// ---------------- y_len tail ----------------
__global__ void ylen_k(float* __restrict__ out, const int* __restrict__ x_len, ll out_size) {
    int i = threadIdx.x;
    if (i < Bn) {
        ll pos = (ll)NTOK * D + i;
        if (pos < out_size) {
            int yl = (x_len[i] + 1) / 2;
            yl = (yl + 1) / 2;
            out[pos] = (float)yl;
        }
    }
}

// ---------------- host launcher ----------------
extern "C" void kernel_launch(void* const* d_in, const int* in_sizes, int n_in,
                              void* d_out, int out_size) {
    const float* x        = (const float*)d_in[0];
    const int*   x_len    = (const int*)  d_in[1];
    const float* conv1_w  = (const float*)d_in[2];
    const float* conv1_b  = (const float*)d_in[3];
    const float* conv2_w  = (const float*)d_in[4];
    const float* conv2_b  = (const float*)d_in[5];
    const float* attn_ln_w= (const float*)d_in[6];
    const float* attn_ln_b= (const float*)d_in[7];
    const float* q_w      = (const float*)d_in[8];
    const float* q_b      = (const float*)d_in[9];
    const float* k_w      = (const float*)d_in[10];
    const float* v_w      = (const float*)d_in[11];
    const float* v_b      = (const float*)d_in[12];
    const float* out_w    = (const float*)d_in[13];
    const float* out_b    = (const float*)d_in[14];
    const float* mlp_ln_w = (const float*)d_in[15];
    const float* mlp_ln_b = (const float*)d_in[16];
    const float* mlp1_w   = (const float*)d_in[17];
    const float* mlp1_b   = (const float*)d_in[18];
    const float* mlp2_w   = (const float*)d_in[19];
    const float* mlp2_b   = (const float*)d_in[20];

    cudaFuncSetAttribute(gemm_tc, cudaFuncAttributeMaxDynamicSharedMemorySize, SMEM_TOT);
    cudaFuncSetAttribute(attn_k,  cudaFuncAttributeMaxDynamicSharedMemorySize, FSM_BYTES);

    #define SYM(p, s) do { void* _t; cudaGetSymbolAddress(&_t, s); p = (decltype(p))_t; } while (0)
    float *xs;
    SYM(xs, g_x);
    half *ph1, *pc1, *pc2, *pwq, *pwk, *pwv, *pwo, *pw1, *pw2;
    half *pcol, *py, *pq, *pk, *pvt, *pm1, *po;
    SYM(ph1, g_h1);
    SYM(pc1, c1w); SYM(pc2, c2w);
    SYM(pwq, wq); SYM(pwk, wk); SYM(pwv, wv); SYM(pwo, wo);
    SYM(pw1, w1); SYM(pw2, w2);
    SYM(pcol, g_col); SYM(py, g_y); SYM(pq, g_q); SYM(pk, g_k);
    SYM(pvt, g_vt); SYM(pm1, g_m1); SYM(po, g_o);

    auto cvt = [&](const float* in, half* out, ll n) {
        cvt_k<<<(int)((n / 4 + 255) / 256), 256>>>(in, out, n);
    };
    cvt(conv1_w, pc1, (ll)D * 384);
    cvt(conv2_w, pc2, (ll)D * 3072);
    cvt(q_w,   pwq, (ll)Ldim * D * D);
    cvt(k_w,   pwk, (ll)Ldim * D * D);
    cvt(v_w,   pwv, (ll)Ldim * D * D);
    cvt(out_w, pwo, (ll)Ldim * D * D);
    cvt(mlp1_w, pw1, (ll)Ldim * Fdim * D);
    cvt(mlp2_w, pw2, (ll)Ldim * Fdim * D);

    auto gemm = [&](const half* A, const half* B,
                    float* C, half* Cs, const float* bias,
                    int M, int N, int K, int lda, int ldb, int ldc,
                    int nz, int zDiv,
                    ll sAo, ll sAi, ll sBo, ll sBi, ll sCo, ll sCi,
                    int biasMode, int addC, int act, int transStore,
                    int outF32, int outHalf, const float* Cin = 0) {
        GemmP p;
        p.A = A; p.B = B;
        p.C = C; p.Cs = Cs; p.Cin = Cin; p.bias = bias;
        p.K = K; p.lda = lda; p.ldb = ldb; p.ldc = ldc;
        p.zDiv = zDiv;
        p.sAo = sAo; p.sAi = sAi; p.sBo = sBo; p.sBi = sBi; p.sCo = sCo; p.sCi = sCi;
        p.biasMode = biasMode; p.addC = addC; p.act = act;
        p.transStore = transStore;
        p.outF32 = outF32; p.outHalf = outHalf;
        dim3 g(N / 128, M / 128, nz);
        gemm_tc<<<g, 512, SMEM_TOT>>>(p);
    };

    const ll SD = (ll)S * D;

    // conv1
    im2col1_k<<<(Bn * T1 * 384 + 255) / 256, 256>>>(x);
    gemm(pcol, pc1, 0, ph1, conv1_b,
         T1, 1024, 384, 384, 384, D,
         Bn, 1, (ll)T1 * 384, 0, 0, 0, (ll)T1 * D, 0,
         1, 0, 1, 0, 0, 1);

    // conv2
    im2col2_k<<<(int)(((ll)Bn * S * 3072 + 255) / 256), 256>>>();
    gemm(pcol, pc2, xs, 0, conv2_b,
         S, 1024, 3072, 3072, 3072, D,
         Bn, 1, (ll)S * 3072, 0, 0, 0, SD, 0,
         1, 0, 1, 0, 1, 0);

    for (int l = 0; l < 6; l++) {
        const float* aw = attn_ln_w + l * D;  const float* ab = attn_ln_b + l * D;
        const float* qb = q_b + l * D;
        const float* vb = v_b + l * D;
        const float* ob = out_b + l * D;
        const float* mw = mlp_ln_w + l * D;   const float* mb2 = mlp_ln_b + l * D;
        const float* b1 = mlp1_b + l * Fdim;
        const float* b2 = mlp2_b + l * D;
        ll wOff = (ll)l * D * D;
        ll mOff = (ll)l * Fdim * D;

        ln_k<<<NTOK, 256>>>(xs, aw, ab);

        // q, k (RoPE+scale epilogue, fp16); v (transposed [d][tok], fp16)
        gemm(py, pwq + wOff, 0, pq, qb,
             NTOK, D, D, D, D, D, 1, 1, 0,0,0,0,0,0, 1, 0, 2, 0, 0, 1);
        gemm(py, pwk + wOff, 0, pk, 0,
             NTOK, D, D, D, D, D, 1, 1, 0,0,0,0,0,0, 0, 0, 2, 0, 0, 1);
        gemm(py, pwv + wOff, 0, pvt, vb,
             NTOK, D, D, D, D, NTOK, 1, 1, 0,0,0,0,0,0, 1, 0, 0, 1, 0, 1);

        // fused flash attention -> g_o fp16
        attn_k<<<dim3(S / 128, Bn * H), 256, FSM_BYTES>>>(x_len);

        // out projection + residual
        gemm(po, pwo + wOff, xs, 0, ob,
             NTOK, D, D, D, D, D, 1, 1, 0,0,0,0,0,0, 1, 1, 0, 0, 1, 0);

        // MLP (last layer's mlp2 writes directly to d_out, residual read from g_x)
        ln_k<<<NTOK, 256>>>(xs, mw, mb2);
        gemm(py, pw1 + mOff, 0, pm1, b1,
             NTOK, Fdim, D, D, D, Fdim, 1, 1, 0,0,0,0,0,0, 1, 0, 1, 0, 0, 1);
        if (l < 5) {
            gemm(pm1, pw2 + mOff, xs, 0, b2,
                 NTOK, D, Fdim, Fdim, Fdim, D, 1, 1, 0,0,0,0,0,0, 1, 1, 0, 0, 1, 0);
        } else {
            gemm(pm1, pw2 + mOff, (float*)d_out, 0, b2,
                 NTOK, D, Fdim, Fdim, Fdim, D, 1, 1, 0,0,0,0,0,0, 1, 1, 0, 0, 1, 0, xs);
        }
    }

    ylen_k<<<1, 32>>>((float*)d_out, x_len, (ll)out_size);
}

// round 12
// speedup vs baseline: 1.0391x; 1.0008x over previous
#include <cuda_runtime.h>
#include <cuda_fp16.h>
#include <math.h>

typedef long long ll;
typedef unsigned u32;

#define Bn 8
#define NMELS 128
#define TIN 4096
#define T1 2048
#define S 1024
#define D 1024
#define H 8
#define DH 128
#define Fdim 4096
#define NTOK (Bn*S)
#define Ldim 6

// ---------------- fp32 scratch ----------------
__device__ float g_x [(size_t)NTOK*D];             // residual stream

// ---------------- fp16 buffers ----------------
__device__ __align__(256) half g_h1[(size_t)Bn*T1*D];   // conv1 out [b][t][d]
__device__ __align__(256) half c1w[(size_t)D*384];
__device__ __align__(256) half c2w[(size_t)D*3072];     // reordered: [d][kk*1024+i]
__device__ __align__(256) half wq[(size_t)Ldim*D*D];
__device__ __align__(256) half wk[(size_t)Ldim*D*D];
__device__ __align__(256) half wv[(size_t)Ldim*D*D];
__device__ __align__(256) half wo[(size_t)Ldim*D*D];
__device__ __align__(256) half w1[(size_t)Ldim*Fdim*D];
__device__ __align__(256) half w2[(size_t)Ldim*Fdim*D];
__device__ __align__(256) half g_col[(size_t)Bn*T1*384];
__device__ __align__(256) half g_y [(size_t)NTOK*D];
__device__ __align__(256) half g_q [(size_t)NTOK*D];
__device__ __align__(256) half g_k [(size_t)NTOK*D];
__device__ __align__(256) half g_vt[(size_t)D*NTOK];
__device__ __align__(256) half g_m1[(size_t)NTOK*Fdim];
__device__ __align__(256) half g_o [(size_t)NTOK*D];

// ---------------- helpers ----------------
__device__ __forceinline__ float gelu_exact(float v) {
    return 0.5f * v * (1.0f + erff(v * 0.70710678118654752f));
}
__device__ __forceinline__ void mma_fp16(float* d, const u32* a, const u32* b) {
    asm volatile(
        "mma.sync.aligned.m16n8k16.row.col.f32.f16.f16.f32 "
        "{%0,%1,%2,%3}, {%4,%5,%6,%7}, {%8,%9}, {%0,%1,%2,%3};\n"
        : "+f"(d[0]), "+f"(d[1]), "+f"(d[2]), "+f"(d[3])
        : "r"(a[0]), "r"(a[1]), "r"(a[2]), "r"(a[3]), "r"(b[0]), "r"(b[1]));
}
__device__ __forceinline__ void ldsm4(u32* r, u32 addr) {
    asm volatile("ldmatrix.sync.aligned.m8n8.x4.shared.b16 {%0,%1,%2,%3}, [%4];\n"
        : "=r"(r[0]), "=r"(r[1]), "=r"(r[2]), "=r"(r[3]) : "r"(addr));
}
__device__ __forceinline__ void cpa16(u32 dst, const void* src) {
    asm volatile("cp.async.cg.shared.global [%0], [%1], 16;\n" :: "r"(dst), "l"(src));
}
__device__ __forceinline__ void cpa16p(u32 dst, const void* src, int pred) {
    int sz = pred ? 16 : 0;
    asm volatile("cp.async.cg.shared.global [%0], [%1], 16, %2;\n" :: "r"(dst), "l"(src), "r"(sz));
}
__device__ __forceinline__ u32 packh2(float lo, float hi) {
    __half2 h = __floats2half2_rn(lo, hi);
    return *(u32*)&h;
}

// ---------------- fp16 tensor-core GEMM (16 warps, KC=64, 3-stage cp.async) ----------------
// C[M,N] = A[M,K] * B[N,K]^T
#define KC 64
#define NSTG 3
#define PADR 72                      // smem row stride (halves)
#define TILE_E (128*PADR)            // 9216 halves
#define TILE_B2 (TILE_E*2)           // 18432 bytes
#define STG_B  (2*TILE_B2)           // 36864
#define SMEM_TOT (NSTG*STG_B)        // 110592

struct GemmP {
    const half *A, *B;
    float* C; half *Cs;
    const float* Cin;   // residual source (defaults to C)
    const float* bias;
    int K, lda, ldb, ldc;
    int zDiv;
    ll sAo, sAi, sBo, sBi, sCo, sCi;
    int biasMode;   // 0 none, 1 per-col(n), 2 per-row(m)
    int addC;
    int act;        // 0 none, 1 exact GELU, 2 RoPE+scale
    int transStore;
    int outF32, outHalf;
    int aConv;      // A is h1 [b][pos][i], col r'=kk*1024+i, pos=2*row+kk-1
};

__global__ __launch_bounds__(512, 1) void gemm_tc(GemmP p) {
    extern __shared__ __align__(16) half sm[];
    int z = blockIdx.z;
    ll offA = (ll)(z / p.zDiv) * p.sAo + (ll)(z % p.zDiv) * p.sAi;
    ll offB = (ll)(z / p.zDiv) * p.sBo + (ll)(z % p.zDiv) * p.sBi;
    ll offC = (ll)(z / p.zDiv) * p.sCo + (ll)(z % p.zDiv) * p.sCi;
    const half* A = p.A + offA;
    const half* B = p.B + offB;

    int m0 = blockIdx.y * 128, n0 = blockIdx.x * 128;
    int tid = threadIdx.x, lane = tid & 31, wid = tid >> 5;
    int wm = (wid & 3) * 32, wn = (wid >> 2) * 32;
    u32 smu = (u32)__cvta_generic_to_shared(sm);

    float acc[2][4][4];
    #pragma unroll
    for (int a = 0; a < 2; a++)
        #pragma unroll
        for (int b = 0; b < 4; b++)
            #pragma unroll
            for (int c = 0; c < 4; c++) acc[a][b][c] = 0.f;

    int ldRow = tid >> 3;           // 0..63
    int ldCC  = (tid & 7) * 8;      // col within 64

    auto issue = [&](int c) {
        u32 base = smu + (u32)(c % NSTG) * STG_B;
        int k0 = c * KC;
        #pragma unroll
        for (int hh = 0; hh < 2; hh++) {
            int row = ldRow + hh * 64;
            u32 so = (u32)(row * PADR + ldCC) * 2;
            if (p.aConv) {
                int kk = k0 >> 10;
                int i0 = (k0 & 1023) + ldCC;
                int pos = 2 * (m0 + row) + kk - 1;
                const half* src = A + (ll)(pos < 0 ? 0 : pos) * 1024 + i0;
                cpa16p(base + so, src, pos >= 0);
            } else {
                cpa16(base + so, A + (ll)(m0 + row) * p.lda + k0 + ldCC);
            }
            cpa16(base + TILE_B2 + so, B + (ll)(n0 + row) * p.ldb + k0 + ldCC);
        }
        asm volatile("cp.async.commit_group;" ::: "memory");
    };

    int nch = p.K / KC;
    issue(0);
    if (nch > 1) issue(1);

    for (int c = 0; c < nch; c++) {
        if (c + 1 < nch) asm volatile("cp.async.wait_group 1;" ::: "memory");
        else             asm volatile("cp.async.wait_group 0;" ::: "memory");
        __syncthreads();
        if (c + 2 < nch) issue(c + 2);

        u32 aB = smu + (u32)(c % NSTG) * STG_B;
        u32 bB = aB + TILE_B2;

        #pragma unroll
        for (int ks = 0; ks < 4; ks++) {
            u32 ar[2][4], br[4][2];
            #pragma unroll
            for (int mi = 0; mi < 2; mi++) {
                int row = wm + mi * 16 + (lane & 15);
                int col = ks * 16 + (lane >> 4) * 8;
                ldsm4(ar[mi], aB + (u32)(row * PADR + col) * 2);
            }
            #pragma unroll
            for (int nj = 0; nj < 2; nj++) {
                int g = lane >> 3;
                int row = wn + nj * 16 + ((g >> 1) << 3) + (lane & 7);
                int col = ks * 16 + ((g & 1) << 3);
                u32 t[4];
                ldsm4(t, bB + (u32)(row * PADR + col) * 2);
                br[nj*2][0] = t[0]; br[nj*2][1] = t[1];
                br[nj*2+1][0] = t[2]; br[nj*2+1][1] = t[3];
            }
            #pragma unroll
            for (int mi = 0; mi < 2; mi++)
                #pragma unroll
                for (int nf = 0; nf < 4; nf++)
                    mma_fp16(acc[mi][nf], ar[mi], br[nf]);
        }
    }

    float* Cp = p.C  ? p.C  + offC : nullptr;
    half* Csp = p.Cs ? p.Cs + offC : nullptr;
    const float* Rp = p.Cin ? p.Cin + offC : Cp;
    #pragma unroll
    for (int mi = 0; mi < 2; mi++)
        #pragma unroll
        for (int nf = 0; nf < 4; nf++) {
            int rB = m0 + wm + mi * 16 + (lane >> 2);
            int cB = n0 + wn + nf * 8 + (lane & 3) * 2;
            #pragma unroll
            for (int pe = 0; pe < 2; pe++) {
                int m = rB + pe * 8;
                float v0 = acc[mi][nf][pe * 2 + 0];
                float v1 = acc[mi][nf][pe * 2 + 1];
                if (p.biasMode == 1) { v0 += p.bias[cB]; v1 += p.bias[cB + 1]; }
                else if (p.biasMode == 2) { float bb = p.bias[m]; v0 += bb; v1 += bb; }
                if (p.act == 1) { v0 = gelu_exact(v0); v1 = gelu_exact(v1); }
                else if (p.act == 2) {
                    int s = m & (S - 1);
                    int j = (cB & 127) >> 1;
                    float freq = powf(10000.f, -(float)(2 * j) * (1.f / 128.f));
                    float ang = (float)s * freq;
                    float cc, ss; sincosf(ang, &ss, &cc);
                    const float sc = 0.29730177875068026f;  // 128^-0.25
                    float r0 = (v0 * cc - v1 * ss) * sc;
                    float r1 = (v0 * ss + v1 * cc) * sc;
                    v0 = r0; v1 = r1;
                }
                if (!p.transStore) {
                    ll off0 = (ll)m * p.ldc + cB;
                    if (p.outF32) {
                        float w0 = v0, w1 = v1;
                        if (p.addC) {
                            float2 o = *(const float2*)&Rp[off0];
                            w0 += o.x; w1 += o.y;
                        }
                        *(float2*)&Cp[off0] = make_float2(w0, w1);
                    }
                    if (p.outHalf) *(u32*)&Csp[off0] = packh2(v0, v1);
                } else {
                    ll off0 = (ll)cB * p.ldc + m;
                    ll off1 = off0 + p.ldc;
                    if (p.outF32) {
                        float w0 = v0, w1 = v1;
                        if (p.addC) { w0 += Rp[off0]; w1 += Rp[off1]; }
                        Cp[off0] = w0; Cp[off1] = w1;
                    }
                    if (p.outHalf) {
                        Csp[off0] = __float2half_rn(v0);
                        Csp[off1] = __float2half_rn(v1);
                    }
                }
            }
        }
}

// ---------------- fused flash attention ----------------
// grid (S/128, Bn*H); 256 threads (8 warps x 16 rows); kv tiles of 128.
#define FP2 136
#define FSM_BYTES ((128+128+128)*FP2*2)    // 104448

__global__ __launch_bounds__(256) void attn_k(const int* __restrict__ x_len) {
    extern __shared__ __align__(16) half fsm[];
    int tid = threadIdx.x, lane = tid & 31, wid = tid >> 5;
    int bh = blockIdx.y, b = bh >> 3, h = bh & 7;
    int m0 = blockIdx.x * 128;
    int wm = wid * 16;
    u32 smu = (u32)__cvta_generic_to_shared(fsm);
    u32 sQ = smu;
    u32 sK = smu + (u32)(128 * FP2) * 2;
    u32 sV = sK + (u32)(128 * FP2) * 2;

    const half* qp = g_q + ((ll)(b * S + m0)) * D + h * 128;
    const half* kp = g_k + ((ll)b * S) * D + h * 128;
    const half* vp = g_vt + ((ll)(h * 128)) * NTOK + (ll)b * S;

    #pragma unroll
    for (int i = 0; i < 8; i++) {
        int idx = tid + 256 * i, row = idx >> 4, ch = idx & 15;
        cpa16(sQ + (u32)(row * FP2 + ch * 8) * 2, qp + (ll)row * D + ch * 8);
    }
    asm volatile("cp.async.commit_group;" ::: "memory");

    int xl = x_len[b];
    int quad = lane >> 2, qi = lane & 3;
    float mrow[2] = {-1e30f, -1e30f}, lrow[2] = {0.f, 0.f};
    float oacc[16][4];
    #pragma unroll
    for (int nt = 0; nt < 16; nt++)
        #pragma unroll
        for (int e = 0; e < 4; e++) oacc[nt][e] = 0.f;

    for (int kv0 = 0; kv0 < S; kv0 += 128) {
        if (kv0) __syncthreads();
        #pragma unroll
        for (int i = 0; i < 8; i++) {
            int idx = tid + 256 * i, row = idx >> 4, ch = idx & 15;
            cpa16(sK + (u32)(row * FP2 + ch * 8) * 2, kp + (ll)(kv0 + row) * D + ch * 8);
        }
        asm volatile("cp.async.commit_group;" ::: "memory");
        #pragma unroll
        for (int i = 0; i < 8; i++) {
            int idx = tid + 256 * i, row = idx >> 4, ch = idx & 15;
            cpa16(sV + (u32)(row * FP2 + ch * 8) * 2, vp + (ll)row * NTOK + kv0 + ch * 8);
        }
        asm volatile("cp.async.commit_group;" ::: "memory");
        asm volatile("cp.async.wait_group 1;" ::: "memory");
        __syncthreads();

        float sacc[16][4];
        #pragma unroll
        for (int nt = 0; nt < 16; nt++)
            #pragma unroll
            for (int e = 0; e < 4; e++) sacc[nt][e] = 0.f;

        #pragma unroll
        for (int ks = 0; ks < 8; ks++) {
            u32 aq[4];
            ldsm4(aq, sQ + (u32)((wm + (lane & 15)) * FP2 + ks * 16 + (lane >> 4) * 8) * 2);
            #pragma unroll
            for (int njp = 0; njp < 8; njp++) {
                int g = lane >> 3;
                int row = njp * 16 + ((g >> 1) << 3) + (lane & 7);
                int col = ks * 16 + ((g & 1) << 3);
                u32 t[4];
                ldsm4(t, sK + (u32)(row * FP2 + col) * 2);
                u32 b0[2] = {t[0], t[1]}, b1[2] = {t[2], t[3]};
                mma_fp16(sacc[njp*2],   aq, b0);
                mma_fp16(sacc[njp*2+1], aq, b1);
            }
        }

        float rmax[2] = {-1e30f, -1e30f};
        #pragma unroll
        for (int nt = 0; nt < 16; nt++)
            #pragma unroll
            for (int e = 0; e < 4; e++) {
                int col = kv0 + nt * 8 + qi * 2 + (e & 1);
                float v = sacc[nt][e] + ((4 * col + 3 < xl) ? 0.f : -1e10f);
                sacc[nt][e] = v;
                rmax[e >> 1] = fmaxf(rmax[e >> 1], v);
            }
        #pragma unroll
        for (int s2 = 1; s2 < 4; s2 <<= 1) {
            rmax[0] = fmaxf(rmax[0], __shfl_xor_sync(0xffffffff, rmax[0], s2));
            rmax[1] = fmaxf(rmax[1], __shfl_xor_sync(0xffffffff, rmax[1], s2));
        }
        float mn0 = fmaxf(mrow[0], rmax[0]), mn1 = fmaxf(mrow[1], rmax[1]);
        float sc0 = expf(mrow[0] - mn0), sc1 = expf(mrow[1] - mn1);
        float rsum[2] = {0.f, 0.f};
        #pragma unroll
        for (int nt = 0; nt < 16; nt++)
            #pragma unroll
            for (int e = 0; e < 4; e++) {
                float v = expf(sacc[nt][e] - ((e >> 1) ? mn1 : mn0));
                sacc[nt][e] = v;
                rsum[e >> 1] += v;
            }
        #pragma unroll
        for (int s2 = 1; s2 < 4; s2 <<= 1) {
            rsum[0] += __shfl_xor_sync(0xffffffff, rsum[0], s2);
            rsum[1] += __shfl_xor_sync(0xffffffff, rsum[1], s2);
        }
        lrow[0] = lrow[0] * sc0 + rsum[0];
        lrow[1] = lrow[1] * sc1 + rsum[1];
        mrow[0] = mn0; mrow[1] = mn1;
        #pragma unroll
        for (int nt = 0; nt < 16; nt++) {
            oacc[nt][0] *= sc0; oacc[nt][1] *= sc0;
            oacc[nt][2] *= sc1; oacc[nt][3] *= sc1;
        }

        asm volatile("cp.async.wait_group 0;" ::: "memory");
        __syncthreads();

        #pragma unroll
        for (int j = 0; j < 8; j++) {
            u32 af[4];
            af[0] = packh2(sacc[2*j][0],   sacc[2*j][1]);
            af[1] = packh2(sacc[2*j][2],   sacc[2*j][3]);
            af[2] = packh2(sacc[2*j+1][0], sacc[2*j+1][1]);
            af[3] = packh2(sacc[2*j+1][2], sacc[2*j+1][3]);
            #pragma unroll
            for (int njp = 0; njp < 8; njp++) {
                int g = lane >> 3;
                int row = njp * 16 + ((g >> 1) << 3) + (lane & 7);
                int col = j * 16 + ((g & 1) << 3);
                u32 t[4];
                ldsm4(t, sV + (u32)(row * FP2 + col) * 2);
                u32 b0[2] = {t[0], t[1]}, b1[2] = {t[2], t[3]};
                mma_fp16(oacc[njp*2],   af, b0);
                mma_fp16(oacc[njp*2+1], af, b1);
            }
        }
    }

    float inv0 = 1.f / lrow[0], inv1 = 1.f / lrow[1];
    half* op = g_o + ((ll)(b * S + m0 + wm)) * D + h * 128;
    #pragma unroll
    for (int nt = 0; nt < 16; nt++)
        #pragma unroll
        for (int pe = 0; pe < 2; pe++) {
            int row = quad + pe * 8;
            float iv = pe ? inv1 : inv0;
            u32 pk = packh2(oacc[nt][pe*2] * iv, oacc[nt][pe*2+1] * iv);
            *(u32*)&op[(ll)row * D + nt * 8 + qi * 2] = pk;
        }
}

// ---------------- weight converts ----------------
__global__ void cvt_k(const float* __restrict__ in, half* __restrict__ out, ll n) {
    ll i = ((ll)blockIdx.x * 256 + threadIdx.x) * 4;
    if (i >= n) return;
    float4 v = *(const float4*)&in[i];
    out[i+0] = __float2half_rn(v.x);
    out[i+1] = __float2half_rn(v.y);
    out[i+2] = __float2half_rn(v.z);
    out[i+3] = __float2half_rn(v.w);
}
// conv2 weights: out[d][kk*1024+i] = in[d][i*3+kk]
__global__ void cvt_c2_k(const float* __restrict__ in, half* __restrict__ out) {
    ll idx = (ll)blockIdx.x * 256 + threadIdx.x;
    if (idx >= (ll)D * 3072) return;
    int rp = (int)(idx % 3072);
    int d  = (int)(idx / 3072);
    int kk = rp >> 10, i = rp & 1023;
    out[idx] = __float2half_rn(in[(ll)d * 3072 + i * 3 + kk]);
}

// ---------------- im2col for conv1 ----------------
__global__ void im2col1_k(const float* __restrict__ x) {
    int idx = blockIdx.x * 256 + threadIdx.x;
    const int total = Bn * T1 * 384;
    if (idx >= total) return;
    int r = idx % 384;
    int t = (idx / 384) % T1;
    int b = idx / (384 * T1);
    int i = r / 3, kk = r % 3;
    int pos = 2 * t + kk - 1;
    float v = (pos >= 0 && pos < TIN) ? x[((ll)b * NMELS + i) * TIN + pos] : 0.f;
    g_col[idx] = __float2half_rn(v);
}

// ---------------- LayerNorm -> fp16 ----------------
__global__ void ln_k(const float* __restrict__ x,
                     const float* __restrict__ w, const float* __restrict__ b) {
    int row = blockIdx.x;
    int tid = threadIdx.x;
    const float* xr = x + (ll)row * D;
    __shared__ float red[256];
    float v[4];
    #pragma unroll
    for (int i = 0; i < 4; i++) v[i] = xr[tid + 256 * i];
    float s = v[0] + v[1] + v[2] + v[3];
    red[tid] = s; __syncthreads();
    for (int o = 128; o > 0; o >>= 1) { if (tid < o) red[tid] += red[tid + o]; __syncthreads(); }
    float mean = red[0] * (1.f / D);
    __syncthreads();
    float sq = 0.f;
    #pragma unroll
    for (int i = 0; i < 4; i++) { float d0 = v[i] - mean; sq += d0 * d0; }
    red[tid] = sq; __syncthreads();
    for (int o = 128; o > 0; o >>= 1) { if (tid < o) red[tid] += red[tid + o]; __syncthreads(); }
    float rstd = rsqrtf(red[0] * (1.f / D) + 1e-5f);
    #pragma unroll
    for (int i = 0; i < 4; i++) {
        int c = tid + 256 * i;
        float y = (v[i] - mean) * rstd * w[c] + b[c];
        g_y[(ll)row * D + c] = __float2half_rn(y);
    }
}

// ---------------- y_len tail ----------------
__global__ void ylen_k(float* __restrict__ out, const int* __restrict__ x_len, ll out_size) {
    int i = threadIdx.x;
    if (i < Bn) {
        ll pos = (ll)NTOK * D + i;
        if (pos < out_size) {
            int yl = (x_len[i] + 1) / 2;
            yl = (yl + 1) / 2;
            out[pos] = (float)yl;
        }
    }
}

// ---------------- host launcher ----------------
extern "C" void kernel_launch(void* const* d_in, const int* in_sizes, int n_in,
                              void* d_out, int out_size) {
    const float* x        = (const float*)d_in[0];
    const int*   x_len    = (const int*)  d_in[1];
    const float* conv1_w  = (const float*)d_in[2];
    const float* conv1_b  = (const float*)d_in[3];
    const float* conv2_w  = (const float*)d_in[4];
    const float* conv2_b  = (const float*)d_in[5];
    const float* attn_ln_w= (const float*)d_in[6];
    const float* attn_ln_b= (const float*)d_in[7];
    const float* q_w      = (const float*)d_in[8];
    const float* q_b      = (const float*)d_in[9];
    const float* k_w      = (const float*)d_in[10];
    const float* v_w      = (const float*)d_in[11];
    const float* v_b      = (const float*)d_in[12];
    const float* out_w    = (const float*)d_in[13];
    const float* out_b    = (const float*)d_in[14];
    const float* mlp_ln_w = (const float*)d_in[15];
    const float* mlp_ln_b = (const float*)d_in[16];
    const float* mlp1_w   = (const float*)d_in[17];
    const float* mlp1_b   = (const float*)d_in[18];
    const float* mlp2_w   = (const float*)d_in[19];
    const float* mlp2_b   = (const float*)d_in[20];

    cudaFuncSetAttribute(gemm_tc, cudaFuncAttributeMaxDynamicSharedMemorySize, SMEM_TOT);
    cudaFuncSetAttribute(attn_k,  cudaFuncAttributeMaxDynamicSharedMemorySize, FSM_BYTES);

    // streams/events for q/k/v fork (created once, before any capture)
    static cudaStream_t s1 = 0, s2 = 0;
    static cudaEvent_t ev0 = 0, ev1 = 0, ev2 = 0;
    if (!s1) {
        cudaStreamCreateWithFlags(&s1, cudaStreamNonBlocking);
        cudaStreamCreateWithFlags(&s2, cudaStreamNonBlocking);
        cudaEventCreateWithFlags(&ev0, cudaEventDisableTiming);
        cudaEventCreateWithFlags(&ev1, cudaEventDisableTiming);
        cudaEventCreateWithFlags(&ev2, cudaEventDisableTiming);
    }

    #define SYM(p, s) do { void* _t; cudaGetSymbolAddress(&_t, s); p = (decltype(p))_t; } while (0)
    float *xs;
    SYM(xs, g_x);
    half *ph1, *pc1, *pc2, *pwq, *pwk, *pwv, *pwo, *pw1, *pw2;
    half *pcol, *py, *pq, *pk, *pvt, *pm1, *po;
    SYM(ph1, g_h1);
    SYM(pc1, c1w); SYM(pc2, c2w);
    SYM(pwq, wq); SYM(pwk, wk); SYM(pwv, wv); SYM(pwo, wo);
    SYM(pw1, w1); SYM(pw2, w2);
    SYM(pcol, g_col); SYM(py, g_y); SYM(pq, g_q); SYM(pk, g_k);
    SYM(pvt, g_vt); SYM(pm1, g_m1); SYM(po, g_o);

    auto cvt = [&](const float* in, half* out, ll n) {
        cvt_k<<<(int)((n / 4 + 255) / 256), 256>>>(in, out, n);
    };
    cvt(conv1_w, pc1, (ll)D * 384);
    cvt_c2_k<<<(int)(((ll)D * 3072 + 255) / 256), 256>>>(conv2_w, pc2);
    cvt(q_w,   pwq, (ll)Ldim * D * D);
    cvt(k_w,   pwk, (ll)Ldim * D * D);
    cvt(v_w,   pwv, (ll)Ldim * D * D);
    cvt(out_w, pwo, (ll)Ldim * D * D);
    cvt(mlp1_w, pw1, (ll)Ldim * Fdim * D);
    cvt(mlp2_w, pw2, (ll)Ldim * Fdim * D);

    auto gemm = [&](cudaStream_t st, const half* A, const half* B,
                    float* C, half* Cs, const float* bias,
                    int M, int N, int K, int lda, int ldb, int ldc,
                    int nz, int zDiv,
                    ll sAo, ll sAi, ll sBo, ll sBi, ll sCo, ll sCi,
                    int biasMode, int addC, int act, int transStore,
                    int outF32, int outHalf, const float* Cin = 0, int aConv = 0) {
        GemmP p;
        p.A = A; p.B = B;
        p.C = C; p.Cs = Cs; p.Cin = Cin; p.bias = bias;
        p.K = K; p.lda = lda; p.ldb = ldb; p.ldc = ldc;
        p.zDiv = zDiv;
        p.sAo = sAo; p.sAi = sAi; p.sBo = sBo; p.sBi = sBi; p.sCo = sCo; p.sCi = sCi;
        p.biasMode = biasMode; p.addC = addC; p.act = act;
        p.transStore = transStore;
        p.outF32 = outF32; p.outHalf = outHalf; p.aConv = aConv;
        dim3 g(N / 128, M / 128, nz);
        gemm_tc<<<g, 512, SMEM_TOT, st>>>(p);
    };

    const ll SD = (ll)S * D;

    // conv1: im2col + GEMM -> g_h1 fp16
    im2col1_k<<<(Bn * T1 * 384 + 255) / 256, 256>>>(x);
    gemm(0, pcol, pc1, 0, ph1, conv1_b,
         T1, 1024, 384, 384, 384, D,
         Bn, 1, (ll)T1 * 384, 0, 0, 0, (ll)T1 * D, 0,
         1, 0, 1, 0, 0, 1);

    // conv2: direct read from g_h1 (kk-major K, zero-fill boundary) -> g_x fp32
    gemm(0, ph1, pc2, xs, 0, conv2_b,
         S, 1024, 3072, 1024, 3072, D,
         Bn, 1, (ll)T1 * D, 0, 0, 0, SD, 0,
         1, 0, 1, 0, 1, 0, 0, 1);

    for (int l = 0; l < 6; l++) {
        const float* aw = attn_ln_w + l * D;  const float* ab = attn_ln_b + l * D;
        const float* qb = q_b + l * D;
        const float* vb = v_b + l * D;
        const float* ob = out_b + l * D;
        const float* mw = mlp_ln_w + l * D;   const float* mb2 = mlp_ln_b + l * D;
        const float* b1 = mlp1_b + l * Fdim;
        const float* b2 = mlp2_b + l * D;
        ll wOff = (ll)l * D * D;
        ll mOff = (ll)l * Fdim * D;

        ln_k<<<NTOK, 256>>>(xs, aw, ab);

        // fork k, v onto side streams; q on default
        cudaEventRecord(ev0, 0);
        cudaStreamWaitEvent(s1, ev0, 0);
        cudaStreamWaitEvent(s2, ev0, 0);
        gemm(s1, py, pwk + wOff, 0, pk, 0,
             NTOK, D, D, D, D, D, 1, 1, 0,0,0,0,0,0, 0, 0, 2, 0, 0, 1);
        cudaEventRecord(ev1, s1);
        gemm(s2, py, pwv + wOff, 0, pvt, vb,
             NTOK, D, D, D, D, NTOK, 1, 1, 0,0,0,0,0,0, 1, 0, 0, 1, 0, 1);
        cudaEventRecord(ev2, s2);
        gemm(0, py, pwq + wOff, 0, pq, qb,
             NTOK, D, D, D, D, D, 1, 1, 0,0,0,0,0,0, 1, 0, 2, 0, 0, 1);
        cudaStreamWaitEvent(0, ev1, 0);
        cudaStreamWaitEvent(0, ev2, 0);

        // fused flash attention -> g_o fp16
        attn_k<<<dim3(S / 128, Bn * H), 256, FSM_BYTES>>>(x_len);

        // out projection + residual
        gemm(0, po, pwo + wOff, xs, 0, ob,
             NTOK, D, D, D, D, D, 1, 1, 0,0,0,0,0,0, 1, 1, 0, 0, 1, 0);

        // MLP (last layer's mlp2 writes directly to d_out)
        ln_k<<<NTOK, 256>>>(xs, mw, mb2);
        gemm(0, py, pw1 + mOff, 0, pm1, b1,
             NTOK, Fdim, D, D, D, Fdim, 1, 1, 0,0,0,0,0,0, 1, 0, 1, 0, 0, 1);
        if (l < 5) {
            gemm(0, pm1, pw2 + mOff, xs, 0, b2,
                 NTOK, D, Fdim, Fdim, Fdim, D, 1, 1, 0,0,0,0,0,0, 1, 1, 0, 0, 1, 0);
        } else {
            gemm(0, pm1, pw2 + mOff, (float*)d_out, 0, b2,
                 NTOK, D, Fdim, Fdim, Fdim, D, 1, 1, 0,0,0,0,0,0, 1, 1, 0, 0, 1, 0, xs);
        }
    }

    ylen_k<<<1, 32>>>((float*)d_out, x_len, (ll)out_size);
}

// round 13
// speedup vs baseline: 1.0856x; 1.0447x over previous
#include <cuda_runtime.h>
#include <cuda_fp16.h>
#include <math.h>

typedef long long ll;
typedef unsigned u32;

#define Bn 8
#define NMELS 128
#define TIN 4096
#define T1 2048
#define S 1024
#define D 1024
#define H 8
#define DH 128
#define Fdim 4096
#define NTOK (Bn*S)
#define Ldim 6

// ---------------- fp32 scratch ----------------
__device__ float g_x [(size_t)NTOK*D];             // residual stream

// ---------------- fp16 buffers ----------------
__device__ __align__(256) half g_h1[(size_t)Bn*T1*D];   // conv1 out [b][t][d]
__device__ __align__(256) half c1w[(size_t)D*384];
__device__ __align__(256) half c2w[(size_t)D*3072];     // reordered: [d][kk*1024+i]
__device__ __align__(256) half wq[(size_t)Ldim*D*D];
__device__ __align__(256) half wk[(size_t)Ldim*D*D];
__device__ __align__(256) half wv[(size_t)Ldim*D*D];
__device__ __align__(256) half wo[(size_t)Ldim*D*D];
__device__ __align__(256) half w1[(size_t)Ldim*Fdim*D];
__device__ __align__(256) half w2[(size_t)Ldim*Fdim*D];
__device__ __align__(256) half g_col[(size_t)Bn*T1*384];
__device__ __align__(256) half g_y [(size_t)NTOK*D];
__device__ __align__(256) half g_q [(size_t)NTOK*D];
__device__ __align__(256) half g_k [(size_t)NTOK*D];
__device__ __align__(256) half g_vt[(size_t)D*NTOK];
__device__ __align__(256) half g_m1[(size_t)NTOK*Fdim];
__device__ __align__(256) half g_o [(size_t)NTOK*D];

// ---------------- helpers ----------------
__device__ __forceinline__ float gelu_exact(float v) {
    return 0.5f * v * (1.0f + erff(v * 0.70710678118654752f));
}
__device__ __forceinline__ void mma_fp16(float* d, const u32* a, const u32* b) {
    asm volatile(
        "mma.sync.aligned.m16n8k16.row.col.f32.f16.f16.f32 "
        "{%0,%1,%2,%3}, {%4,%5,%6,%7}, {%8,%9}, {%0,%1,%2,%3};\n"
        : "+f"(d[0]), "+f"(d[1]), "+f"(d[2]), "+f"(d[3])
        : "r"(a[0]), "r"(a[1]), "r"(a[2]), "r"(a[3]), "r"(b[0]), "r"(b[1]));
}
__device__ __forceinline__ void ldsm4(u32* r, u32 addr) {
    asm volatile("ldmatrix.sync.aligned.m8n8.x4.shared.b16 {%0,%1,%2,%3}, [%4];\n"
        : "=r"(r[0]), "=r"(r[1]), "=r"(r[2]), "=r"(r[3]) : "r"(addr));
}
__device__ __forceinline__ void cpa16(u32 dst, const void* src) {
    asm volatile("cp.async.cg.shared.global [%0], [%1], 16;\n" :: "r"(dst), "l"(src));
}
__device__ __forceinline__ void cpa16p(u32 dst, const void* src, int pred) {
    int sz = pred ? 16 : 0;
    asm volatile("cp.async.cg.shared.global [%0], [%1], 16, %2;\n" :: "r"(dst), "l"(src), "r"(sz));
}
__device__ __forceinline__ u32 packh2(float lo, float hi) {
    __half2 h = __floats2half2_rn(lo, hi);
    return *(u32*)&h;
}

// ---------------- fp16 tensor-core GEMM (16 warps, KC=64, 3-stage cp.async) ----------------
// C[M,N] = A[M,K] * B[N,K]^T
#define KC 64
#define NSTG 3
#define PADR 72
#define TILE_E (128*PADR)
#define TILE_B2 (TILE_E*2)
#define STG_B  (2*TILE_B2)
#define SMEM_TOT (NSTG*STG_B)        // 110592

struct GemmP {
    const half *A, *B;
    const half *Bk, *Bv;     // qkvZ weight pointers for z=1,2
    float* C; half *Cs;
    half *Qd, *Kd, *Vd;      // qkvZ outputs
    const float* Cin;
    const float* bias;
    const float* bias2;      // qkvZ: v bias
    int K, lda, ldb, ldc;
    int zDiv;
    ll sAo, sAi, sBo, sBi, sCo, sCi;
    int biasMode;   // 0 none, 1 per-col(n), 2 per-row(m)
    int addC;
    int act;        // 0 none, 1 exact GELU, 2 RoPE+scale
    int transStore;
    int outF32, outHalf;
    int aConv;
    int qkvZ;       // grid.z selects q/k/v
};

__device__ __forceinline__ void rope2(float& v0, float& v1, int m, int cB) {
    int s = m & (S - 1);
    int j = (cB & 127) >> 1;
    float freq = powf(10000.f, -(float)(2 * j) * (1.f / 128.f));
    float ang = (float)s * freq;
    float cc, ss; sincosf(ang, &ss, &cc);
    const float sc = 0.29730177875068026f;  // 128^-0.25
    float r0 = (v0 * cc - v1 * ss) * sc;
    float r1 = (v0 * ss + v1 * cc) * sc;
    v0 = r0; v1 = r1;
}

__global__ __launch_bounds__(512, 1) void gemm_tc(GemmP p) {
    extern __shared__ __align__(16) half sm[];
    int z = blockIdx.z;
    ll offA = 0, offB = 0, offC = 0;
    const half* A = p.A;
    const half* B = p.B;
    if (p.qkvZ) {
        B = (z == 0) ? p.B : (z == 1) ? p.Bk : p.Bv;
    } else {
        offA = (ll)(z / p.zDiv) * p.sAo + (ll)(z % p.zDiv) * p.sAi;
        offB = (ll)(z / p.zDiv) * p.sBo + (ll)(z % p.zDiv) * p.sBi;
        offC = (ll)(z / p.zDiv) * p.sCo + (ll)(z % p.zDiv) * p.sCi;
        A += offA; B += offB;
    }

    int m0 = blockIdx.y * 128, n0 = blockIdx.x * 128;
    int tid = threadIdx.x, lane = tid & 31, wid = tid >> 5;
    int wm = (wid & 3) * 32, wn = (wid >> 2) * 32;
    u32 smu = (u32)__cvta_generic_to_shared(sm);

    float acc[2][4][4];
    #pragma unroll
    for (int a = 0; a < 2; a++)
        #pragma unroll
        for (int b = 0; b < 4; b++)
            #pragma unroll
            for (int c = 0; c < 4; c++) acc[a][b][c] = 0.f;

    int ldRow = tid >> 3;
    int ldCC  = (tid & 7) * 8;

    auto issue = [&](int c) {
        u32 base = smu + (u32)(c % NSTG) * STG_B;
        int k0 = c * KC;
        #pragma unroll
        for (int hh = 0; hh < 2; hh++) {
            int row = ldRow + hh * 64;
            u32 so = (u32)(row * PADR + ldCC) * 2;
            if (p.aConv) {
                int kk = k0 >> 10;
                int i0 = (k0 & 1023) + ldCC;
                int pos = 2 * (m0 + row) + kk - 1;
                const half* src = A + (ll)(pos < 0 ? 0 : pos) * 1024 + i0;
                cpa16p(base + so, src, pos >= 0);
            } else {
                cpa16(base + so, A + (ll)(m0 + row) * p.lda + k0 + ldCC);
            }
            cpa16(base + TILE_B2 + so, B + (ll)(n0 + row) * p.ldb + k0 + ldCC);
        }
        asm volatile("cp.async.commit_group;" ::: "memory");
    };

    int nch = p.K / KC;
    issue(0);
    if (nch > 1) issue(1);

    for (int c = 0; c < nch; c++) {
        if (c + 1 < nch) asm volatile("cp.async.wait_group 1;" ::: "memory");
        else             asm volatile("cp.async.wait_group 0;" ::: "memory");
        __syncthreads();
        if (c + 2 < nch) issue(c + 2);

        u32 aB = smu + (u32)(c % NSTG) * STG_B;
        u32 bB = aB + TILE_B2;

        #pragma unroll
        for (int ks = 0; ks < 4; ks++) {
            u32 ar[2][4], br[4][2];
            #pragma unroll
            for (int mi = 0; mi < 2; mi++) {
                int row = wm + mi * 16 + (lane & 15);
                int col = ks * 16 + (lane >> 4) * 8;
                ldsm4(ar[mi], aB + (u32)(row * PADR + col) * 2);
            }
            #pragma unroll
            for (int nj = 0; nj < 2; nj++) {
                int g = lane >> 3;
                int row = wn + nj * 16 + ((g >> 1) << 3) + (lane & 7);
                int col = ks * 16 + ((g & 1) << 3);
                u32 t[4];
                ldsm4(t, bB + (u32)(row * PADR + col) * 2);
                br[nj*2][0] = t[0]; br[nj*2][1] = t[1];
                br[nj*2+1][0] = t[2]; br[nj*2+1][1] = t[3];
            }
            #pragma unroll
            for (int mi = 0; mi < 2; mi++)
                #pragma unroll
                for (int nf = 0; nf < 4; nf++)
                    mma_fp16(acc[mi][nf], ar[mi], br[nf]);
        }
    }

    float* Cp = p.C  ? p.C  + offC : nullptr;
    half* Csp = p.Cs ? p.Cs + offC : nullptr;
    const float* Rp = p.Cin ? p.Cin + offC : Cp;
    #pragma unroll
    for (int mi = 0; mi < 2; mi++)
        #pragma unroll
        for (int nf = 0; nf < 4; nf++) {
            int rB = m0 + wm + mi * 16 + (lane >> 2);
            int cB = n0 + wn + nf * 8 + (lane & 3) * 2;
            #pragma unroll
            for (int pe = 0; pe < 2; pe++) {
                int m = rB + pe * 8;
                float v0 = acc[mi][nf][pe * 2 + 0];
                float v1 = acc[mi][nf][pe * 2 + 1];

                if (p.qkvZ) {
                    if (z == 0) {
                        v0 += p.bias[cB]; v1 += p.bias[cB + 1];
                        rope2(v0, v1, m, cB);
                        *(u32*)&p.Qd[(ll)m * D + cB] = packh2(v0, v1);
                    } else if (z == 1) {
                        rope2(v0, v1, m, cB);
                        *(u32*)&p.Kd[(ll)m * D + cB] = packh2(v0, v1);
                    } else {
                        v0 += p.bias2[cB]; v1 += p.bias2[cB + 1];
                        p.Vd[(ll)cB * NTOK + m]       = __float2half_rn(v0);
                        p.Vd[(ll)(cB + 1) * NTOK + m] = __float2half_rn(v1);
                    }
                    continue;
                }

                if (p.biasMode == 1) { v0 += p.bias[cB]; v1 += p.bias[cB + 1]; }
                else if (p.biasMode == 2) { float bb = p.bias[m]; v0 += bb; v1 += bb; }
                if (p.act == 1) { v0 = gelu_exact(v0); v1 = gelu_exact(v1); }
                else if (p.act == 2) rope2(v0, v1, m, cB);

                if (!p.transStore) {
                    ll off0 = (ll)m * p.ldc + cB;
                    if (p.outF32) {
                        float w0 = v0, w1 = v1;
                        if (p.addC) {
                            float2 o = *(const float2*)&Rp[off0];
                            w0 += o.x; w1 += o.y;
                        }
                        *(float2*)&Cp[off0] = make_float2(w0, w1);
                    }
                    if (p.outHalf) *(u32*)&Csp[off0] = packh2(v0, v1);
                } else {
                    ll off0 = (ll)cB * p.ldc + m;
                    ll off1 = off0 + p.ldc;
                    if (p.outF32) {
                        float w0 = v0, w1 = v1;
                        if (p.addC) { w0 += Rp[off0]; w1 += Rp[off1]; }
                        Cp[off0] = w0; Cp[off1] = w1;
                    }
                    if (p.outHalf) {
                        Csp[off0] = __float2half_rn(v0);
                        Csp[off1] = __float2half_rn(v1);
                    }
                }
            }
        }
}

// ---------------- fused flash attention ----------------
#define FP2 136
#define FSM_BYTES ((128+128+128)*FP2*2)    // 104448

__global__ __launch_bounds__(256) void attn_k(const int* __restrict__ x_len) {
    extern __shared__ __align__(16) half fsm[];
    int tid = threadIdx.x, lane = tid & 31, wid = tid >> 5;
    int bh = blockIdx.y, b = bh >> 3, h = bh & 7;
    int m0 = blockIdx.x * 128;
    int wm = wid * 16;
    u32 smu = (u32)__cvta_generic_to_shared(fsm);
    u32 sQ = smu;
    u32 sK = smu + (u32)(128 * FP2) * 2;
    u32 sV = sK + (u32)(128 * FP2) * 2;

    const half* qp = g_q + ((ll)(b * S + m0)) * D + h * 128;
    const half* kp = g_k + ((ll)b * S) * D + h * 128;
    const half* vp = g_vt + ((ll)(h * 128)) * NTOK + (ll)b * S;

    #pragma unroll
    for (int i = 0; i < 8; i++) {
        int idx = tid + 256 * i, row = idx >> 4, ch = idx & 15;
        cpa16(sQ + (u32)(row * FP2 + ch * 8) * 2, qp + (ll)row * D + ch * 8);
    }
    asm volatile("cp.async.commit_group;" ::: "memory");

    int xl = x_len[b];
    int quad = lane >> 2, qi = lane & 3;
    float mrow[2] = {-1e30f, -1e30f}, lrow[2] = {0.f, 0.f};
    float oacc[16][4];
    #pragma unroll
    for (int nt = 0; nt < 16; nt++)
        #pragma unroll
        for (int e = 0; e < 4; e++) oacc[nt][e] = 0.f;

    for (int kv0 = 0; kv0 < S; kv0 += 128) {
        if (kv0) __syncthreads();
        #pragma unroll
        for (int i = 0; i < 8; i++) {
            int idx = tid + 256 * i, row = idx >> 4, ch = idx & 15;
            cpa16(sK + (u32)(row * FP2 + ch * 8) * 2, kp + (ll)(kv0 + row) * D + ch * 8);
        }
        asm volatile("cp.async.commit_group;" ::: "memory");
        #pragma unroll
        for (int i = 0; i < 8; i++) {
            int idx = tid + 256 * i, row = idx >> 4, ch = idx & 15;
            cpa16(sV + (u32)(row * FP2 + ch * 8) * 2, vp + (ll)row * NTOK + kv0 + ch * 8);
        }
        asm volatile("cp.async.commit_group;" ::: "memory");
        asm volatile("cp.async.wait_group 1;" ::: "memory");
        __syncthreads();

        float sacc[16][4];
        #pragma unroll
        for (int nt = 0; nt < 16; nt++)
            #pragma unroll
            for (int e = 0; e < 4; e++) sacc[nt][e] = 0.f;

        #pragma unroll
        for (int ks = 0; ks < 8; ks++) {
            u32 aq[4];
            ldsm4(aq, sQ + (u32)((wm + (lane & 15)) * FP2 + ks * 16 + (lane >> 4) * 8) * 2);
            #pragma unroll
            for (int njp = 0; njp < 8; njp++) {
                int g = lane >> 3;
                int row = njp * 16 + ((g >> 1) << 3) + (lane & 7);
                int col = ks * 16 + ((g & 1) << 3);
                u32 t[4];
                ldsm4(t, sK + (u32)(row * FP2 + col) * 2);
                u32 b0[2] = {t[0], t[1]}, b1[2] = {t[2], t[3]};
                mma_fp16(sacc[njp*2],   aq, b0);
                mma_fp16(sacc[njp*2+1], aq, b1);
            }
        }

        float rmax[2] = {-1e30f, -1e30f};
        #pragma unroll
        for (int nt = 0; nt < 16; nt++)
            #pragma unroll
            for (int e = 0; e < 4; e++) {
                int col = kv0 + nt * 8 + qi * 2 + (e & 1);
                float v = sacc[nt][e] + ((4 * col + 3 < xl) ? 0.f : -1e10f);
                sacc[nt][e] = v;
                rmax[e >> 1] = fmaxf(rmax[e >> 1], v);
            }
        #pragma unroll
        for (int s2 = 1; s2 < 4; s2 <<= 1) {
            rmax[0] = fmaxf(rmax[0], __shfl_xor_sync(0xffffffff, rmax[0], s2));
            rmax[1] = fmaxf(rmax[1], __shfl_xor_sync(0xffffffff, rmax[1], s2));
        }
        float mn0 = fmaxf(mrow[0], rmax[0]), mn1 = fmaxf(mrow[1], rmax[1]);
        float sc0 = expf(mrow[0] - mn0), sc1 = expf(mrow[1] - mn1);
        float rsum[2] = {0.f, 0.f};
        #pragma unroll
        for (int nt = 0; nt < 16; nt++)
            #pragma unroll
            for (int e = 0; e < 4; e++) {
                float v = expf(sacc[nt][e] - ((e >> 1) ? mn1 : mn0));
                sacc[nt][e] = v;
                rsum[e >> 1] += v;
            }
        #pragma unroll
        for (int s2 = 1; s2 < 4; s2 <<= 1) {
            rsum[0] += __shfl_xor_sync(0xffffffff, rsum[0], s2);
            rsum[1] += __shfl_xor_sync(0xffffffff, rsum[1], s2);
        }
        lrow[0] = lrow[0] * sc0 + rsum[0];
        lrow[1] = lrow[1] * sc1 + rsum[1];
        mrow[0] = mn0; mrow[1] = mn1;
        #pragma unroll
        for (int nt = 0; nt < 16; nt++) {
            oacc[nt][0] *= sc0; oacc[nt][1] *= sc0;
            oacc[nt][2] *= sc1; oacc[nt][3] *= sc1;
        }

        asm volatile("cp.async.wait_group 0;" ::: "memory");
        __syncthreads();

        #pragma unroll
        for (int j = 0; j < 8; j++) {
            u32 af[4];
            af[0] = packh2(sacc[2*j][0],   sacc[2*j][1]);
            af[1] = packh2(sacc[2*j][2],   sacc[2*j][3]);
            af[2] = packh2(sacc[2*j+1][0], sacc[2*j+1][1]);
            af[3] = packh2(sacc[2*j+1][2], sacc[2*j+1][3]);
            #pragma unroll
            for (int njp = 0; njp < 8; njp++) {
                int g = lane >> 3;
                int row = njp * 16 + ((g >> 1) << 3) + (lane & 7);
                int col = j * 16 + ((g & 1) << 3);
                u32 t[4];
                ldsm4(t, sV + (u32)(row * FP2 + col) * 2);
                u32 b0[2] = {t[0], t[1]}, b1[2] = {t[2], t[3]};
                mma_fp16(oacc[njp*2],   af, b0);
                mma_fp16(oacc[njp*2+1], af, b1);
            }
        }
    }

    float inv0 = 1.f / lrow[0], inv1 = 1.f / lrow[1];
    half* op = g_o + ((ll)(b * S + m0 + wm)) * D + h * 128;
    #pragma unroll
    for (int nt = 0; nt < 16; nt++)
        #pragma unroll
        for (int pe = 0; pe < 2; pe++) {
            int row = quad + pe * 8;
            float iv = pe ? inv1 : inv0;
            u32 pk = packh2(oacc[nt][pe*2] * iv, oacc[nt][pe*2+1] * iv);
            *(u32*)&op[(ll)row * D + nt * 8 + qi * 2] = pk;
        }
}

// ---------------- weight converts (8 elems/thread, packed 16B store) ----------------
__global__ void cvt_k(const float* __restrict__ in, half* __restrict__ out, ll n) {
    ll i = ((ll)blockIdx.x * 256 + threadIdx.x) * 8;
    if (i >= n) return;
    float4 a = *(const float4*)&in[i];
    float4 b = *(const float4*)&in[i + 4];
    uint4 o;
    o.x = packh2(a.x, a.y);
    o.y = packh2(a.z, a.w);
    o.z = packh2(b.x, b.y);
    o.w = packh2(b.z, b.w);
    *(uint4*)&out[i] = o;
}
// conv2 weights: out[d][kk*1024+i] = in[d][i*3+kk]
__global__ void cvt_c2_k(const float* __restrict__ in, half* __restrict__ out) {
    ll idx = (ll)blockIdx.x * 256 + threadIdx.x;
    if (idx >= (ll)D * 3072) return;
    int rp = (int)(idx % 3072);
    int d  = (int)(idx / 3072);
    int kk = rp >> 10, i = rp & 1023;
    out[idx] = __float2half_rn(in[(ll)d * 3072 + i * 3 + kk]);
}

// ---------------- im2col for conv1 ----------------
__global__ void im2col1_k(const float* __restrict__ x) {
    int idx = blockIdx.x * 256 + threadIdx.x;
    const int total = Bn * T1 * 384;
    if (idx >= total) return;
    int r = idx % 384;
    int t = (idx / 384) % T1;
    int b = idx / (384 * T1);
    int i = r / 3, kk = r % 3;
    int pos = 2 * t + kk - 1;
    float v = (pos >= 0 && pos < TIN) ? x[((ll)b * NMELS + i) * TIN + pos] : 0.f;
    g_col[idx] = __float2half_rn(v);
}

// ---------------- LayerNorm -> fp16 ----------------
__global__ void ln_k(const float* __restrict__ x,
                     const float* __restrict__ w, const float* __restrict__ b) {
    int row = blockIdx.x;
    int tid = threadIdx.x;
    const float* xr = x + (ll)row * D;
    __shared__ float red[256];
    float v[4];
    #pragma unroll
    for (int i = 0; i < 4; i++) v[i] = xr[tid + 256 * i];
    float s = v[0] + v[1] + v[2] + v[3];
    red[tid] = s; __syncthreads();
    for (int o = 128; o > 0; o >>= 1) { if (tid < o) red[tid] += red[tid + o]; __syncthreads(); }
    float mean = red[0] * (1.f / D);
    __syncthreads();
    float sq = 0.f;
    #pragma unroll
    for (int i = 0; i < 4; i++) { float d0 = v[i] - mean; sq += d0 * d0; }
    red[tid] = sq; __syncthreads();
    for (int o = 128; o > 0; o >>= 1) { if (tid < o) red[tid] += red[tid + o]; __syncthreads(); }
    float rstd = rsqrtf(red[0] * (1.f / D) + 1e-5f);
    #pragma unroll
    for (int i = 0; i < 4; i++) {
        int c = tid + 256 * i;
        float y = (v[i] - mean) * rstd * w[c] + b[c];
        g_y[(ll)row * D + c] = __float2half_rn(y);
    }
}

// ---------------- y_len tail ----------------
__global__ void ylen_k(float* __restrict__ out, const int* __restrict__ x_len, ll out_size) {
    int i = threadIdx.x;
    if (i < Bn) {
        ll pos = (ll)NTOK * D + i;
        if (pos < out_size) {
            int yl = (x_len[i] + 1) / 2;
            yl = (yl + 1) / 2;
            out[pos] = (float)yl;
        }
    }
}

// ---------------- host launcher ----------------
extern "C" void kernel_launch(void* const* d_in, const int* in_sizes, int n_in,
                              void* d_out, int out_size) {
    const float* x        = (const float*)d_in[0];
    const int*   x_len    = (const int*)  d_in[1];
    const float* conv1_w  = (const float*)d_in[2];
    const float* conv1_b  = (const float*)d_in[3];
    const float* conv2_w  = (const float*)d_in[4];
    const float* conv2_b  = (const float*)d_in[5];
    const float* attn_ln_w= (const float*)d_in[6];
    const float* attn_ln_b= (const float*)d_in[7];
    const float* q_w      = (const float*)d_in[8];
    const float* q_b      = (const float*)d_in[9];
    const float* k_w      = (const float*)d_in[10];
    const float* v_w      = (const float*)d_in[11];
    const float* v_b      = (const float*)d_in[12];
    const float* out_w    = (const float*)d_in[13];
    const float* out_b    = (const float*)d_in[14];
    const float* mlp_ln_w = (const float*)d_in[15];
    const float* mlp_ln_b = (const float*)d_in[16];
    const float* mlp1_w   = (const float*)d_in[17];
    const float* mlp1_b   = (const float*)d_in[18];
    const float* mlp2_w   = (const float*)d_in[19];
    const float* mlp2_b   = (const float*)d_in[20];

    cudaFuncSetAttribute(gemm_tc, cudaFuncAttributeMaxDynamicSharedMemorySize, SMEM_TOT);
    cudaFuncSetAttribute(attn_k,  cudaFuncAttributeMaxDynamicSharedMemorySize, FSM_BYTES);

    #define SYM(p, s) do { void* _t; cudaGetSymbolAddress(&_t, s); p = (decltype(p))_t; } while (0)
    float *xs;
    SYM(xs, g_x);
    half *ph1, *pc1, *pc2, *pwq, *pwk, *pwv, *pwo, *pw1, *pw2;
    half *pcol, *py, *pq, *pk, *pvt, *pm1, *po;
    SYM(ph1, g_h1);
    SYM(pc1, c1w); SYM(pc2, c2w);
    SYM(pwq, wq); SYM(pwk, wk); SYM(pwv, wv); SYM(pwo, wo);
    SYM(pw1, w1); SYM(pw2, w2);
    SYM(pcol, g_col); SYM(py, g_y); SYM(pq, g_q); SYM(pk, g_k);
    SYM(pvt, g_vt); SYM(pm1, g_m1); SYM(po, g_o);

    auto cvt = [&](const float* in, half* out, ll n) {
        cvt_k<<<(int)((n / 8 + 255) / 256), 256>>>(in, out, n);
    };
    cvt(conv1_w, pc1, (ll)D * 384);
    cvt_c2_k<<<(int)(((ll)D * 3072 + 255) / 256), 256>>>(conv2_w, pc2);
    cvt(q_w,   pwq, (ll)Ldim * D * D);
    cvt(k_w,   pwk, (ll)Ldim * D * D);
    cvt(v_w,   pwv, (ll)Ldim * D * D);
    cvt(out_w, pwo, (ll)Ldim * D * D);
    cvt(mlp1_w, pw1, (ll)Ldim * Fdim * D);
    cvt(mlp2_w, pw2, (ll)Ldim * Fdim * D);

    auto gemm = [&](const half* A, const half* B,
                    float* C, half* Cs, const float* bias,
                    int M, int N, int K, int lda, int ldb, int ldc,
                    int nz, int zDiv,
                    ll sAo, ll sAi, ll sBo, ll sBi, ll sCo, ll sCi,
                    int biasMode, int addC, int act, int transStore,
                    int outF32, int outHalf, const float* Cin = 0, int aConv = 0) {
        GemmP p = {};
        p.A = A; p.B = B;
        p.C = C; p.Cs = Cs; p.Cin = Cin; p.bias = bias;
        p.K = K; p.lda = lda; p.ldb = ldb; p.ldc = ldc;
        p.zDiv = zDiv;
        p.sAo = sAo; p.sAi = sAi; p.sBo = sBo; p.sBi = sBi; p.sCo = sCo; p.sCi = sCi;
        p.biasMode = biasMode; p.addC = addC; p.act = act;
        p.transStore = transStore;
        p.outF32 = outF32; p.outHalf = outHalf; p.aConv = aConv;
        p.qkvZ = 0;
        dim3 g(N / 128, M / 128, nz);
        gemm_tc<<<g, 512, SMEM_TOT>>>(p);
    };

    const ll SD = (ll)S * D;

    // conv1: im2col + GEMM -> g_h1 fp16
    im2col1_k<<<(Bn * T1 * 384 + 255) / 256, 256>>>(x);
    gemm(pcol, pc1, 0, ph1, conv1_b,
         T1, 1024, 384, 384, 384, D,
         Bn, 1, (ll)T1 * 384, 0, 0, 0, (ll)T1 * D, 0,
         1, 0, 1, 0, 0, 1);

    // conv2: direct read from g_h1 (kk-major K, zero-fill boundary) -> g_x fp32
    gemm(ph1, pc2, xs, 0, conv2_b,
         S, 1024, 3072, 1024, 3072, D,
         Bn, 1, (ll)T1 * D, 0, 0, 0, SD, 0,
         1, 0, 1, 0, 1, 0, 0, 1);

    for (int l = 0; l < 6; l++) {
        const float* aw = attn_ln_w + l * D;  const float* ab = attn_ln_b + l * D;
        const float* qb = q_b + l * D;
        const float* vb = v_b + l * D;
        const float* ob = out_b + l * D;
        const float* mw = mlp_ln_w + l * D;   const float* mb2 = mlp_ln_b + l * D;
        const float* b1 = mlp1_b + l * Fdim;
        const float* b2 = mlp2_b + l * D;
        ll wOff = (ll)l * D * D;
        ll mOff = (ll)l * Fdim * D;

        ln_k<<<NTOK, 256>>>(xs, aw, ab);

        // fused qkv: one launch, grid.z selects q/k/v (uniform per-CTA epilogue)
        {
            GemmP p = {};
            p.A = py;
            p.B = pwq + wOff; p.Bk = pwk + wOff; p.Bv = pwv + wOff;
            p.Qd = pq; p.Kd = pk; p.Vd = pvt;
            p.bias = qb; p.bias2 = vb;
            p.K = D; p.lda = D; p.ldb = D; p.ldc = D;
            p.zDiv = 1;
            p.qkvZ = 1;
            dim3 g(D / 128, NTOK / 128, 3);
            gemm_tc<<<g, 512, SMEM_TOT>>>(p);
        }

        // fused flash attention -> g_o fp16
        attn_k<<<dim3(S / 128, Bn * H), 256, FSM_BYTES>>>(x_len);

        // out projection + residual
        gemm(po, pwo + wOff, xs, 0, ob,
             NTOK, D, D, D, D, D, 1, 1, 0,0,0,0,0,0, 1, 1, 0, 0, 1, 0);

        // MLP (last layer's mlp2 writes directly to d_out)
        ln_k<<<NTOK, 256>>>(xs, mw, mb2);
        gemm(py, pw1 + mOff, 0, pm1, b1,
             NTOK, Fdim, D, D, D, Fdim, 1, 1, 0,0,0,0,0,0, 1, 0, 1, 0, 0, 1);
        if (l < 5) {
            gemm(pm1, pw2 + mOff, xs, 0, b2,
                 NTOK, D, Fdim, Fdim, Fdim, D, 1, 1, 0,0,0,0,0,0, 1, 1, 0, 0, 1, 0);
        } else {
            gemm(pm1, pw2 + mOff, (float*)d_out, 0, b2,
                 NTOK, D, Fdim, Fdim, Fdim, D, 1, 1, 0,0,0,0,0,0, 1, 1, 0, 0, 1, 0, xs);
        }
    }

    ylen_k<<<1, 32>>>((float*)d_out, x_len, (ll)out_size);
}